// round 1
// baseline (speedup 1.0000x reference)
#include <cuda_runtime.h>
#include <math.h>

// Problem constants
#define BB   8
#define CC   1024
#define CI_  512
#define HEAD_ 2
#define DD   256          // CI_/HEAD_
#define TT   8
#define HH   28
#define WW   28
#define NTOT 6272         // T*H*W
#define NP   1568         // T*(H/2)*(W/2)
#define BH   16           // BB*HEAD_

// Scratch buffers (device globals: allocation-free)
__device__ float g_xp[(long)BB * CC * NP];        // pooled x      (b, c, n')
__device__ float g_g [(long)BB * CI_ * NP];       // g conv        (b, ci, n')
__device__ float g_ph[(long)BB * CI_ * NP];       // phi conv      (b, ci, n')
__device__ float g_th[(long)BB * CI_ * NTOT];     // theta conv    (b, ci, n)
__device__ float g_y [(long)BB * CI_ * NTOT];     // attention out (b, ci, n)
__device__ float g_f [(long)BH * NTOT * NP];      // scores        (bh, n, n')

// ---------------------------------------------------------------------------
// MaxPool3d(1,2,2) : x (B,C,T,28,28) -> xp (B,C,T,14,14)
// ---------------------------------------------------------------------------
__global__ void maxpool_kernel(const float* __restrict__ x) {
    long idx = (long)blockIdx.x * blockDim.x + threadIdx.x;
    const long total = (long)BB * CC * TT * 14 * 14;
    if (idx >= total) return;
    int ow = idx % 14;
    int oh = (idx / 14) % 14;
    long rest = idx / 196;              // (b*C + c)*T + t
    long base = rest * (HH * WW) + (long)(oh * 2) * WW + ow * 2;
    float m0 = fmaxf(x[base], x[base + 1]);
    float m1 = fmaxf(x[base + WW], x[base + WW + 1]);
    g_xp[idx] = fmaxf(m0, m1);
}

// ---------------------------------------------------------------------------
// Generic strided batched GEMM: C[m,n] = sum_k A[m*am + k*ak] * B[k*bk + n*bn]
// C row-major (M x N, row stride N), batch via z.
// EPI: 0 = +bias[m]; 1 = *scale; 2 = plain; 3 = BN+residual epilogue.
// AMI: A smem load with m innermost (true when am==1). BNI: same for B/n.
// ---------------------------------------------------------------------------
template<int EPI, bool AMI, bool BNI>
__global__ void __launch_bounds__(256)
gemm_kernel(const float* __restrict__ A, long am, long ak, long ab,
            const float* __restrict__ Bp, long bk, long bn, long bb,
            float* __restrict__ Cp, long cb,
            int M, int N, int K,
            const float* __restrict__ bias, float scale,
            const float* __restrict__ gamma, const float* __restrict__ beta,
            const float* __restrict__ rmean, const float* __restrict__ rvar,
            const float* __restrict__ xres, long xb)
{
    __shared__ float As[16][65];
    __shared__ float Bs[16][65];

    const int bz = blockIdx.z;
    const float* Ab = A  + ab * bz;
    const float* Bb = Bp + bb * bz;
    float*       Cb = Cp + cb * bz;

    const int m0 = blockIdx.y * 64;
    const int n0 = blockIdx.x * 64;
    const int tid = threadIdx.x;
    const int ty = tid >> 4;        // 0..15
    const int tx = tid & 15;        // 0..15

    float acc[4][4];
#pragma unroll
    for (int i = 0; i < 4; i++)
#pragma unroll
        for (int j = 0; j < 4; j++) acc[i][j] = 0.f;

    for (int k0 = 0; k0 < K; k0 += 16) {
        // load A tile (64 x 16)
#pragma unroll
        for (int i = 0; i < 4; i++) {
            int e = tid + i * 256;
            int m, k;
            if (AMI) { m = e & 63; k = e >> 6; }
            else     { k = e & 15; m = e >> 4; }
            int gm = m0 + m;
            As[k][m] = (gm < M) ? Ab[(long)gm * am + (long)(k0 + k) * ak] : 0.f;
        }
        // load B tile (16 x 64)
#pragma unroll
        for (int i = 0; i < 4; i++) {
            int e = tid + i * 256;
            int n, k;
            if (BNI) { n = e & 63; k = e >> 6; }
            else     { k = e & 15; n = e >> 4; }
            int gn = n0 + n;
            Bs[k][n] = (gn < N) ? Bb[(long)(k0 + k) * bk + (long)gn * bn] : 0.f;
        }
        __syncthreads();

#pragma unroll
        for (int k = 0; k < 16; k++) {
            float av[4], bv[4];
#pragma unroll
            for (int i = 0; i < 4; i++) av[i] = As[k][ty * 4 + i];
#pragma unroll
            for (int j = 0; j < 4; j++) bv[j] = Bs[k][tx * 4 + j];
#pragma unroll
            for (int i = 0; i < 4; i++)
#pragma unroll
                for (int j = 0; j < 4; j++)
                    acc[i][j] = fmaf(av[i], bv[j], acc[i][j]);
        }
        __syncthreads();
    }

#pragma unroll
    for (int i = 0; i < 4; i++) {
        int m = m0 + ty * 4 + i;
        if (m >= M) continue;
#pragma unroll
        for (int j = 0; j < 4; j++) {
            int n = n0 + tx * 4 + j;
            if (n >= N) continue;
            float v = acc[i][j];
            if (EPI == 0) v += bias[m];
            if (EPI == 1) v *= scale;
            if (EPI == 3) {
                float inv = gamma[m] * rsqrtf(rvar[m] + 1e-5f);
                v = (v + bias[m]) * inv + (beta[m] - rmean[m] * inv)
                    + xres[xb * bz + (long)m * N + n];
            }
            Cb[(long)m * N + n] = v;
        }
    }
}

// ---------------------------------------------------------------------------
// Row softmax, in place. One block per row of width NP.
// ---------------------------------------------------------------------------
__global__ void softmax_kernel(float* __restrict__ f) {
    float* p = f + (long)blockIdx.x * NP;
    const int tid = threadIdx.x;          // 128 threads
    __shared__ float red[128];

    float mx = -INFINITY;
    for (int i = tid; i < NP; i += 128) mx = fmaxf(mx, p[i]);
    red[tid] = mx; __syncthreads();
    for (int s = 64; s > 0; s >>= 1) {
        if (tid < s) red[tid] = fmaxf(red[tid], red[tid + s]);
        __syncthreads();
    }
    mx = red[0]; __syncthreads();

    float sum = 0.f;
    for (int i = tid; i < NP; i += 128) {
        float e = expf(p[i] - mx);
        p[i] = e;
        sum += e;
    }
    red[tid] = sum; __syncthreads();
    for (int s = 64; s > 0; s >>= 1) {
        if (tid < s) red[tid] += red[tid + s];
        __syncthreads();
    }
    float inv = 1.f / red[0];
    for (int i = tid; i < NP; i += 128) p[i] *= inv;
}

// ---------------------------------------------------------------------------
extern "C" void kernel_launch(void* const* d_in, const int* in_sizes, int n_in,
                              void* d_out, int out_size)
{
    const float* x     = (const float*)d_in[0];
    const float* Wg    = (const float*)d_in[1];
    const float* bg    = (const float*)d_in[2];
    const float* Wth   = (const float*)d_in[3];
    const float* bth   = (const float*)d_in[4];
    const float* Wph   = (const float*)d_in[5];
    const float* bph   = (const float*)d_in[6];
    const float* Ww    = (const float*)d_in[7];
    const float* bw    = (const float*)d_in[8];
    const float* gamma = (const float*)d_in[9];
    const float* beta  = (const float*)d_in[10];
    const float* rmean = (const float*)d_in[11];
    const float* rvar  = (const float*)d_in[12];
    float* out = (float*)d_out;

    float *xp, *gbuf, *phbuf, *thbuf, *ybuf, *fbuf;
    cudaGetSymbolAddress((void**)&xp,    g_xp);
    cudaGetSymbolAddress((void**)&gbuf,  g_g);
    cudaGetSymbolAddress((void**)&phbuf, g_ph);
    cudaGetSymbolAddress((void**)&thbuf, g_th);
    cudaGetSymbolAddress((void**)&ybuf,  g_y);
    cudaGetSymbolAddress((void**)&fbuf,  g_f);

    // 1) maxpool
    {
        long total = (long)BB * CC * NP;
        maxpool_kernel<<<(unsigned)((total + 255) / 256), 256>>>(x);
    }

    // 2) g = Wg @ xp + bg       (M=512, N=1568, K=1024, batch 8)
    {
        dim3 grid((NP + 63) / 64, CI_ / 64, BB);
        gemm_kernel<0, false, true><<<grid, 256>>>(
            Wg, CC, 1, 0,
            xp, NP, 1, (long)CC * NP,
            gbuf, (long)CI_ * NP,
            CI_, NP, CC,
            bg, 0.f, nullptr, nullptr, nullptr, nullptr, nullptr, 0);
    }
    // 3) ph = Wph @ xp + bph
    {
        dim3 grid((NP + 63) / 64, CI_ / 64, BB);
        gemm_kernel<0, false, true><<<grid, 256>>>(
            Wph, CC, 1, 0,
            xp, NP, 1, (long)CC * NP,
            phbuf, (long)CI_ * NP,
            CI_, NP, CC,
            bph, 0.f, nullptr, nullptr, nullptr, nullptr, nullptr, 0);
    }
    // 4) th = Wth @ x + bth     (M=512, N=6272, K=1024, batch 8)
    {
        dim3 grid(NTOT / 64, CI_ / 64, BB);
        gemm_kernel<0, false, true><<<grid, 256>>>(
            Wth, CC, 1, 0,
            x, NTOT, 1, (long)CC * NTOT,
            thbuf, (long)CI_ * NTOT,
            CI_, NTOT, CC,
            bth, 0.f, nullptr, nullptr, nullptr, nullptr, nullptr, 0);
    }
    // 5) f = th^T @ ph * d^-0.5  (M=6272, N=1568, K=256, batch 16)
    {
        dim3 grid((NP + 63) / 64, NTOT / 64, BH);
        gemm_kernel<1, true, true><<<grid, 256>>>(
            thbuf, 1, NTOT, (long)DD * NTOT,
            phbuf, NP, 1, (long)DD * NP,
            fbuf, (long)NTOT * NP,
            NTOT, NP, DD,
            nullptr, 0.0625f, nullptr, nullptr, nullptr, nullptr, nullptr, 0);
    }
    // 6) softmax rows (16*6272 rows of 1568)
    softmax_kernel<<<BH * NTOT, 128>>>(fbuf);

    // 7) y = g @ a^T             (M=256, N=6272, K=1568, batch 16)
    {
        dim3 grid(NTOT / 64, DD / 64, BH);
        gemm_kernel<2, false, false><<<grid, 256>>>(
            gbuf, NP, 1, (long)DD * NP,
            fbuf, 1, NP, (long)NTOT * NP,
            ybuf, (long)DD * NTOT,
            DD, NTOT, NP,
            nullptr, 0.f, nullptr, nullptr, nullptr, nullptr, nullptr, 0);
    }
    // 8) out = BN(Ww @ y + bw) + x   (M=1024, N=6272, K=512, batch 8)
    {
        dim3 grid(NTOT / 64, CC / 64, BB);
        gemm_kernel<3, false, true><<<grid, 256>>>(
            Ww, CI_, 1, 0,
            ybuf, NTOT, 1, (long)CI_ * NTOT,
            out, (long)CC * NTOT,
            CC, NTOT, CI_,
            bw, 0.f, gamma, beta, rmean, rvar, x, (long)CC * NTOT);
    }
}

// round 2
// speedup vs baseline: 1.1287x; 1.1287x over previous
#include <cuda_runtime.h>
#include <math.h>

// Problem constants
#define BB   8
#define CC   1024
#define CI_  512
#define HEAD_ 2
#define DD   256          // CI_/HEAD_
#define TT   8
#define HH   28
#define WW   28
#define NTOT 6272         // T*H*W
#define NP   1568         // T*(H/2)*(W/2)
#define BH   16           // BB*HEAD_

// Scratch buffers (device globals: allocation-free)
__device__ float g_xp[(long)BB * CC * NP];        // pooled x      (b, c, n')
__device__ float g_g [(long)BB * CI_ * NP];       // g conv        (b, ci, n')
__device__ float g_ph[(long)BB * CI_ * NP];       // phi conv      (b, ci, n')
__device__ float g_th[(long)BB * CI_ * NTOT];     // theta conv    (b, ci, n)
__device__ float g_y [(long)BB * CI_ * NTOT];     // attention out (b, ci, n)
__device__ float g_f [(long)BH * NTOT * NP];      // scores        (bh, n, n')

// ---------------------------------------------------------------------------
// MaxPool3d(1,2,2) : x (B,C,T,28,28) -> xp (B,C,T,14,14)
// ---------------------------------------------------------------------------
__global__ void maxpool_kernel(const float* __restrict__ x) {
    long idx = (long)blockIdx.x * blockDim.x + threadIdx.x;
    const long total = (long)BB * CC * TT * 14 * 14;
    if (idx >= total) return;
    int ow = idx % 14;
    int oh = (idx / 14) % 14;
    long rest = idx / 196;              // (b*C + c)*T + t
    long base = rest * (HH * WW) + (long)(oh * 2) * WW + ow * 2;
    float m0 = fmaxf(x[base], x[base + 1]);
    float m1 = fmaxf(x[base + WW], x[base + WW + 1]);
    g_xp[idx] = fmaxf(m0, m1);
}

// ---------------------------------------------------------------------------
// Strided batched GEMM, 128x128 tile, 8x8 microtile, double-buffered smem,
// register-staged global->smem pipeline.
// C[m,n] = sum_k A[m*am + k*ak] * B[k*bk + n*bn]
// EPI: 0 = +bias[m]; 1 = *scale; 2 = plain; 3 = BN+residual epilogue.
// AMI: m is the contiguous (innermost) axis of A. BNI: same for B/n.
// ---------------------------------------------------------------------------
template<int EPI, bool AMI, bool BNI>
__global__ void __launch_bounds__(256)
gemm_kernel(const float* __restrict__ A, long am, long ak, long ab,
            const float* __restrict__ Bp, long bk, long bn, long bb,
            float* __restrict__ Cp, long cb,
            int M, int N, int K,
            const float* __restrict__ bias, float scale,
            const float* __restrict__ gamma, const float* __restrict__ beta,
            const float* __restrict__ rmean, const float* __restrict__ rvar,
            const float* __restrict__ xres, long xb)
{
    __shared__ float As[2][16][132];
    __shared__ float Bs[2][16][132];

    const int bz = blockIdx.z;
    const float* Ab = A  + ab * bz;
    const float* Bb = Bp + bb * bz;
    float*       Cb = Cp + cb * bz;

    const int m0 = blockIdx.y * 128;
    const int n0 = blockIdx.x * 128;
    const int tid = threadIdx.x;
    const int ty = tid >> 4;        // 0..15 -> rows m0 + ty*8 .. +7
    const int tx = tid & 15;        // 0..15 -> cols n0 + tx*8 .. +7

    // staging index decomposition (compile-time pattern)
    int a_m[8], a_k[8], b_n[8], b_k[8];
#pragma unroll
    for (int j = 0; j < 8; j++) {
        int e = tid + j * 256;
        if (AMI) { a_m[j] = e & 127; a_k[j] = e >> 7; }
        else     { a_k[j] = e & 15;  a_m[j] = e >> 4; }
        if (BNI) { b_n[j] = e & 127; b_k[j] = e >> 7; }
        else     { b_k[j] = e & 15;  b_n[j] = e >> 4; }
    }

    float acc[8][8];
#pragma unroll
    for (int i = 0; i < 8; i++)
#pragma unroll
        for (int j = 0; j < 8; j++) acc[i][j] = 0.f;

    float ra[8], rb[8];

    // preload k-tile 0 into registers
#pragma unroll
    for (int j = 0; j < 8; j++) {
        int gm = m0 + a_m[j];
        ra[j] = (gm < M) ? Ab[(long)gm * am + (long)a_k[j] * ak] : 0.f;
        int gn = n0 + b_n[j];
        rb[j] = (gn < N) ? Bb[(long)b_k[j] * bk + (long)gn * bn] : 0.f;
    }
    // store to smem buffer 0
#pragma unroll
    for (int j = 0; j < 8; j++) {
        As[0][a_k[j]][a_m[j]] = ra[j];
        Bs[0][b_k[j]][b_n[j]] = rb[j];
    }
    __syncthreads();

    const int KT = K >> 4;
    int cur = 0;
    for (int kt = 0; kt < KT; kt++) {
        // issue global loads for next k-tile
        if (kt + 1 < KT) {
            int k0 = (kt + 1) << 4;
#pragma unroll
            for (int j = 0; j < 8; j++) {
                int gm = m0 + a_m[j];
                ra[j] = (gm < M) ? Ab[(long)gm * am + (long)(k0 + a_k[j]) * ak] : 0.f;
                int gn = n0 + b_n[j];
                rb[j] = (gn < N) ? Bb[(long)(k0 + b_k[j]) * bk + (long)gn * bn] : 0.f;
            }
        }
        // compute on current buffer
#pragma unroll
        for (int k = 0; k < 16; k++) {
            float4 a0 = *(const float4*)&As[cur][k][ty * 8];
            float4 a1 = *(const float4*)&As[cur][k][ty * 8 + 4];
            float4 b0 = *(const float4*)&Bs[cur][k][tx * 8];
            float4 b1 = *(const float4*)&Bs[cur][k][tx * 8 + 4];
            float av[8] = {a0.x, a0.y, a0.z, a0.w, a1.x, a1.y, a1.z, a1.w};
            float bv[8] = {b0.x, b0.y, b0.z, b0.w, b1.x, b1.y, b1.z, b1.w};
#pragma unroll
            for (int i = 0; i < 8; i++)
#pragma unroll
                for (int j = 0; j < 8; j++)
                    acc[i][j] = fmaf(av[i], bv[j], acc[i][j]);
        }
        // stage next tile into the other buffer
        if (kt + 1 < KT) {
            int nxt = cur ^ 1;
#pragma unroll
            for (int j = 0; j < 8; j++) {
                As[nxt][a_k[j]][a_m[j]] = ra[j];
                Bs[nxt][b_k[j]][b_n[j]] = rb[j];
            }
        }
        __syncthreads();
        cur ^= 1;
    }

    // epilogue
#pragma unroll
    for (int i = 0; i < 8; i++) {
        int m = m0 + ty * 8 + i;
        if (m >= M) continue;
        float bi = 0.f, inv = 0.f, sh = 0.f;
        if (EPI == 0) bi = bias[m];
        if (EPI == 3) {
            inv = gamma[m] * rsqrtf(rvar[m] + 1e-5f);
            sh  = beta[m] - rmean[m] * inv;
            bi  = bias[m];
        }
#pragma unroll
        for (int j = 0; j < 8; j++) {
            int n = n0 + tx * 8 + j;
            if (n >= N) continue;
            float v = acc[i][j];
            if (EPI == 0) v += bi;
            if (EPI == 1) v *= scale;
            if (EPI == 3) v = (v + bi) * inv + sh + xres[xb * bz + (long)m * N + n];
            Cb[(long)m * N + n] = v;
        }
    }
}

// ---------------------------------------------------------------------------
// Row softmax, in place. One block per row of width NP.
// ---------------------------------------------------------------------------
__global__ void softmax_kernel(float* __restrict__ f) {
    float* p = f + (long)blockIdx.x * NP;
    const int tid = threadIdx.x;          // 128 threads
    __shared__ float red[128];

    float mx = -INFINITY;
    for (int i = tid; i < NP; i += 128) mx = fmaxf(mx, p[i]);
    red[tid] = mx; __syncthreads();
    for (int s = 64; s > 0; s >>= 1) {
        if (tid < s) red[tid] = fmaxf(red[tid], red[tid + s]);
        __syncthreads();
    }
    mx = red[0]; __syncthreads();

    float sum = 0.f;
    for (int i = tid; i < NP; i += 128) {
        float e = __expf(p[i] - mx);
        p[i] = e;
        sum += e;
    }
    red[tid] = sum; __syncthreads();
    for (int s = 64; s > 0; s >>= 1) {
        if (tid < s) red[tid] += red[tid + s];
        __syncthreads();
    }
    float inv = 1.f / red[0];
    for (int i = tid; i < NP; i += 128) p[i] *= inv;
}

// ---------------------------------------------------------------------------
extern "C" void kernel_launch(void* const* d_in, const int* in_sizes, int n_in,
                              void* d_out, int out_size)
{
    const float* x     = (const float*)d_in[0];
    const float* Wg    = (const float*)d_in[1];
    const float* bg    = (const float*)d_in[2];
    const float* Wth   = (const float*)d_in[3];
    const float* bth   = (const float*)d_in[4];
    const float* Wph   = (const float*)d_in[5];
    const float* bph   = (const float*)d_in[6];
    const float* Ww    = (const float*)d_in[7];
    const float* bw    = (const float*)d_in[8];
    const float* gamma = (const float*)d_in[9];
    const float* beta  = (const float*)d_in[10];
    const float* rmean = (const float*)d_in[11];
    const float* rvar  = (const float*)d_in[12];
    float* out = (float*)d_out;

    float *xp, *gbuf, *phbuf, *thbuf, *ybuf, *fbuf;
    cudaGetSymbolAddress((void**)&xp,    g_xp);
    cudaGetSymbolAddress((void**)&gbuf,  g_g);
    cudaGetSymbolAddress((void**)&phbuf, g_ph);
    cudaGetSymbolAddress((void**)&thbuf, g_th);
    cudaGetSymbolAddress((void**)&ybuf,  g_y);
    cudaGetSymbolAddress((void**)&fbuf,  g_f);

    // 1) maxpool
    {
        long total = (long)BB * CC * NP;
        maxpool_kernel<<<(unsigned)((total + 255) / 256), 256>>>(x);
    }

    // 2) g = Wg @ xp + bg       (M=512, N=1568, K=1024, batch 8)
    {
        dim3 grid((NP + 127) / 128, CI_ / 128, BB);
        gemm_kernel<0, false, true><<<grid, 256>>>(
            Wg, CC, 1, 0,
            xp, NP, 1, (long)CC * NP,
            gbuf, (long)CI_ * NP,
            CI_, NP, CC,
            bg, 0.f, nullptr, nullptr, nullptr, nullptr, nullptr, 0);
    }
    // 3) ph = Wph @ xp + bph
    {
        dim3 grid((NP + 127) / 128, CI_ / 128, BB);
        gemm_kernel<0, false, true><<<grid, 256>>>(
            Wph, CC, 1, 0,
            xp, NP, 1, (long)CC * NP,
            phbuf, (long)CI_ * NP,
            CI_, NP, CC,
            bph, 0.f, nullptr, nullptr, nullptr, nullptr, nullptr, 0);
    }
    // 4) th = Wth @ x + bth     (M=512, N=6272, K=1024, batch 8)
    {
        dim3 grid(NTOT / 128, CI_ / 128, BB);
        gemm_kernel<0, false, true><<<grid, 256>>>(
            Wth, CC, 1, 0,
            x, NTOT, 1, (long)CC * NTOT,
            thbuf, (long)CI_ * NTOT,
            CI_, NTOT, CC,
            bth, 0.f, nullptr, nullptr, nullptr, nullptr, nullptr, 0);
    }
    // 5) f = th^T @ ph * d^-0.5  (M=6272, N=1568, K=256, batch 16)
    {
        dim3 grid((NP + 127) / 128, NTOT / 128, BH);
        gemm_kernel<1, true, true><<<grid, 256>>>(
            thbuf, 1, NTOT, (long)DD * NTOT,
            phbuf, NP, 1, (long)DD * NP,
            fbuf, (long)NTOT * NP,
            NTOT, NP, DD,
            nullptr, 0.0625f, nullptr, nullptr, nullptr, nullptr, nullptr, 0);
    }
    // 6) softmax rows (16*6272 rows of 1568)
    softmax_kernel<<<BH * NTOT, 128>>>(fbuf);

    // 7) y = g @ a^T             (M=256, N=6272, K=1568, batch 16)
    {
        dim3 grid(NTOT / 128, DD / 128, BH);
        gemm_kernel<2, false, false><<<grid, 256>>>(
            gbuf, NP, 1, (long)DD * NP,
            fbuf, 1, NP, (long)NTOT * NP,
            ybuf, (long)DD * NTOT,
            DD, NTOT, NP,
            nullptr, 0.f, nullptr, nullptr, nullptr, nullptr, nullptr, 0);
    }
    // 8) out = BN(Ww @ y + bw) + x   (M=1024, N=6272, K=512, batch 8)
    {
        dim3 grid(NTOT / 128, CC / 128, BB);
        gemm_kernel<3, false, true><<<grid, 256>>>(
            Ww, CI_, 1, 0,
            ybuf, NTOT, 1, (long)CI_ * NTOT,
            out, (long)CC * NTOT,
            CC, NTOT, CI_,
            bw, 0.f, gamma, beta, rmean, rvar, x, (long)CC * NTOT);
    }
}

// round 5
// speedup vs baseline: 1.7074x; 1.5127x over previous
#include <cuda_runtime.h>
#include <math.h>
#include <stdint.h>

// Problem constants
#define BB   8
#define CC   1024
#define CI_  512
#define DD   256
#define TT   8
#define HH   28
#define WW   28
#define NTOT 6272
#define NP   1568
#define BH   16

// Scratch (device globals: allocation-free)
__device__ float g_xp[(long)BB * CC * NP];
__device__ float g_g [(long)BB * CI_ * NP];
__device__ float g_ph[(long)BB * CI_ * NP];
__device__ float g_th[(long)BB * CI_ * NTOT];
__device__ float g_y [(long)BB * CI_ * NTOT];
__device__ float g_f [(long)BH * NTOT * NP];

__device__ __forceinline__ uint32_t f2tf32(float f) {
    uint32_t r;
    asm("cvt.rna.tf32.f32 %0, %1;" : "=r"(r) : "f"(f));
    return r;
}

__device__ __forceinline__ void mma16n8k8(float* c, const uint32_t* a, const uint32_t* b) {
    asm volatile(
        "mma.sync.aligned.m16n8k8.row.col.f32.tf32.tf32.f32 "
        "{%0,%1,%2,%3}, {%4,%5,%6,%7}, {%8,%9}, {%0,%1,%2,%3};"
        : "+f"(c[0]), "+f"(c[1]), "+f"(c[2]), "+f"(c[3])
        : "r"(a[0]), "r"(a[1]), "r"(a[2]), "r"(a[3]), "r"(b[0]), "r"(b[1]));
}

// ---------------------------------------------------------------------------
// MaxPool3d(1,2,2)
// ---------------------------------------------------------------------------
__global__ void maxpool_kernel(const float* __restrict__ x) {
    long idx = (long)blockIdx.x * blockDim.x + threadIdx.x;
    const long total = (long)BB * CC * TT * 14 * 14;
    if (idx >= total) return;
    int ow = idx % 14;
    int oh = (idx / 14) % 14;
    long rest = idx / 196;
    long base = rest * (HH * WW) + (long)(oh * 2) * WW + ow * 2;
    float m0 = fmaxf(x[base], x[base + 1]);
    float m1 = fmaxf(x[base + WW], x[base + WW + 1]);
    g_xp[idx] = fmaxf(m0, m1);
}

// ---------------------------------------------------------------------------
// mma.sync tf32 GEMM: C[m,n] = sum_k A'[m*am + k*ak] * B'[k*bk + n*bn]
// Tiles: BM=128, BN=128, BK=32. 8 warps, warp tile 32(m) x 64(n).
// AKI: k contiguous in A (ak==1) -> A stored [m][k] pad 36 (MK).
//      else A stored [k][m] pad 136 (KM).
// BKI: k contiguous in B (bk==1) -> B stored [n][k] pad 36 (NK).
//      else B stored [k][n] pad 136 (KN).
// EPI: 0=+bias[m]; 1=*scale; 2=plain; 3=BN+residual.
// Requirements: M%128==0, K%32==0, N%4==0 (N edge bounds-checked).
// ---------------------------------------------------------------------------
#define TILE_WORDS 4608      // max(128*36, 32*136)
#define SM_BYTES   (4 * TILE_WORDS * 4)

template<int EPI, bool AKI, bool BKI>
__global__ void __launch_bounds__(256, 1)
tgemm_kernel(const float* __restrict__ A, long am, long ak, long ab,
             const float* __restrict__ Bp, long bk, long bn, long bb,
             float* __restrict__ Cp, long cb,
             int M, int N, int K,
             const float* __restrict__ bias, float scale,
             const float* __restrict__ gamma, const float* __restrict__ beta,
             const float* __restrict__ rmean, const float* __restrict__ rvar,
             const float* __restrict__ xres, long xb)
{
    extern __shared__ float sm[];
    float* Asm[2] = { sm,                  sm + TILE_WORDS };
    float* Bsm[2] = { sm + 2 * TILE_WORDS, sm + 3 * TILE_WORDS };

    const int tid  = threadIdx.x;
    const int wid  = tid >> 5;
    const int lane = tid & 31;
    const int gq   = lane >> 2;   // group id 0..7
    const int qq   = lane & 3;    // quad    0..3
    const int warp_m = (wid & 3) * 32;
    const int warp_n = (wid >> 2) * 64;

    const int bz = blockIdx.z;
    const float* Ab = A  + ab * bz;
    const float* Bb = Bp + bb * bz;
    float*       Cb = Cp + cb * bz;
    const int m0 = blockIdx.y * 128;
    const int n0 = blockIdx.x * 128;

    float acc[2][8][4];
#pragma unroll
    for (int i = 0; i < 2; i++)
#pragma unroll
        for (int j = 0; j < 8; j++)
#pragma unroll
            for (int r = 0; r < 4; r++) acc[i][j][r] = 0.f;

    const int KT = K >> 5;

    uint4 ra[4], rb[4];
    bool  bv[4];

    // --- stage k-tile kt from gmem into registers (tf32-converted) ---
    auto stage = [&](int kt) {
        const int k0 = kt << 5;
#pragma unroll
        for (int j = 0; j < 4; j++) {
            int e = tid + j * 256;
            if (AKI) {
                int m = e >> 3, kq = e & 7;
                float4 v = *(const float4*)(Ab + (long)(m0 + m) * am + (k0 + kq * 4));
                ra[j] = make_uint4(f2tf32(v.x), f2tf32(v.y), f2tf32(v.z), f2tf32(v.w));
            } else {
                int mq = e & 31, kk = e >> 5;
                float4 v = *(const float4*)(Ab + (long)(k0 + kk) * ak + (m0 + mq * 4));
                ra[j] = make_uint4(f2tf32(v.x), f2tf32(v.y), f2tf32(v.z), f2tf32(v.w));
            }
            if (BKI) {
                int n = e >> 3, kq = e & 7;
                bv[j] = (n0 + n) < N;
                if (bv[j]) {
                    float4 v = *(const float4*)(Bb + (long)(n0 + n) * bn + (k0 + kq * 4));
                    rb[j] = make_uint4(f2tf32(v.x), f2tf32(v.y), f2tf32(v.z), f2tf32(v.w));
                }
            } else {
                int nq = e & 31, kk = e >> 5;
                bv[j] = (n0 + nq * 4) < N;
                if (bv[j]) {
                    float4 v = *(const float4*)(Bb + (long)(k0 + kk) * bk + (n0 + nq * 4));
                    rb[j] = make_uint4(f2tf32(v.x), f2tf32(v.y), f2tf32(v.z), f2tf32(v.w));
                }
            }
        }
    };
    // --- commit staged registers into smem buffer ---
    auto commit = [&](int buf) {
        float* pa = Asm[buf];
        float* pb = Bsm[buf];
#pragma unroll
        for (int j = 0; j < 4; j++) {
            int e = tid + j * 256;
            if (AKI) { int m = e >> 3, kq = e & 7;  *(uint4*)(pa + m * 36 + kq * 4) = ra[j]; }
            else     { int mq = e & 31, kk = e >> 5; *(uint4*)(pa + kk * 136 + mq * 4) = ra[j]; }
            if (bv[j]) {
                if (BKI) { int n = e >> 3, kq = e & 7;  *(uint4*)(pb + n * 36 + kq * 4) = rb[j]; }
                else     { int nq = e & 31, kk = e >> 5; *(uint4*)(pb + kk * 136 + nq * 4) = rb[j]; }
            }
        }
    };
    // --- compute one 32-k tile from smem buffer (4 MMA steps of k=8) ---
    auto compute = [&](int buf) {
        const uint32_t* pa = (const uint32_t*)Asm[buf];
        const uint32_t* pb = (const uint32_t*)Bsm[buf];
#pragma unroll
        for (int ks = 0; ks < 4; ks++) {
            const int c = ks * 8 + qq;          // k-base of this MMA step
            uint32_t afr[2][4];
#pragma unroll
            for (int mf = 0; mf < 2; mf++) {
                int r = warp_m + mf * 16 + gq;
                if (AKI) {
                    afr[mf][0] = pa[r * 36 + c];
                    afr[mf][1] = pa[(r + 8) * 36 + c];
                    afr[mf][2] = pa[r * 36 + c + 4];
                    afr[mf][3] = pa[(r + 8) * 36 + c + 4];
                } else {
                    afr[mf][0] = pa[c * 136 + r];
                    afr[mf][1] = pa[c * 136 + r + 8];
                    afr[mf][2] = pa[(c + 4) * 136 + r];
                    afr[mf][3] = pa[(c + 4) * 136 + r + 8];
                }
            }
#pragma unroll
            for (int nf = 0; nf < 8; nf++) {
                uint32_t bfr[2];
                int n = warp_n + nf * 8 + gq;
                if (BKI) {
                    bfr[0] = pb[n * 36 + c];
                    bfr[1] = pb[n * 36 + c + 4];
                } else {
                    bfr[0] = pb[c * 136 + n];
                    bfr[1] = pb[(c + 4) * 136 + n];
                }
                mma16n8k8(acc[0][nf], afr[0], bfr);
                mma16n8k8(acc[1][nf], afr[1], bfr);
            }
        }
    };

    // prologue
    stage(0);
    commit(0);
    __syncthreads();

    for (int kt = 0; kt < KT; kt++) {
        const int buf = kt & 1;
        if (kt + 1 < KT) stage(kt + 1);       // LDG in flight during compute
        compute(buf);
        if (kt + 1 < KT) {
            commit(buf ^ 1);
            __syncthreads();
        }
    }

    // epilogue: direct stores (float2 per fragment row)
#pragma unroll
    for (int mf = 0; mf < 2; mf++) {
        int r1 = m0 + warp_m + mf * 16 + gq;
        int r2 = r1 + 8;
        float b1 = 0.f, b2 = 0.f, i1 = 0.f, i2 = 0.f, s1 = 0.f, s2 = 0.f;
        if (EPI == 0) { b1 = bias[r1]; b2 = bias[r2]; }
        if (EPI == 3) {
            b1 = bias[r1]; b2 = bias[r2];
            i1 = gamma[r1] * rsqrtf(rvar[r1] + 1e-5f);
            i2 = gamma[r2] * rsqrtf(rvar[r2] + 1e-5f);
            s1 = beta[r1] - rmean[r1] * i1;
            s2 = beta[r2] - rmean[r2] * i2;
        }
#pragma unroll
        for (int nf = 0; nf < 8; nf++) {
            int col = n0 + warp_n + nf * 8 + 2 * qq;
            if (col >= N) continue;
            float v0 = acc[mf][nf][0], v1 = acc[mf][nf][1];
            float v2 = acc[mf][nf][2], v3 = acc[mf][nf][3];
            if (EPI == 0) { v0 += b1; v1 += b1; v2 += b2; v3 += b2; }
            if (EPI == 1) { v0 *= scale; v1 *= scale; v2 *= scale; v3 *= scale; }
            if (EPI == 3) {
                const float* xr = xres + xb * bz;
                float2 x1 = *(const float2*)(xr + (long)r1 * N + col);
                float2 x2 = *(const float2*)(xr + (long)r2 * N + col);
                v0 = (v0 + b1) * i1 + s1 + x1.x;
                v1 = (v1 + b1) * i1 + s1 + x1.y;
                v2 = (v2 + b2) * i2 + s2 + x2.x;
                v3 = (v3 + b2) * i2 + s2 + x2.y;
            }
            *(float2*)(Cb + (long)r1 * N + col) = make_float2(v0, v1);
            *(float2*)(Cb + (long)r2 * N + col) = make_float2(v2, v3);
        }
    }
}

// ---------------------------------------------------------------------------
// Row softmax, in place.
// ---------------------------------------------------------------------------
__global__ void softmax_kernel(float* __restrict__ f) {
    float* p = f + (long)blockIdx.x * NP;
    const int tid = threadIdx.x;          // 128 threads
    __shared__ float red[128];

    float mx = -INFINITY;
    for (int i = tid; i < NP; i += 128) mx = fmaxf(mx, p[i]);
    red[tid] = mx; __syncthreads();
    for (int s = 64; s > 0; s >>= 1) {
        if (tid < s) red[tid] = fmaxf(red[tid], red[tid + s]);
        __syncthreads();
    }
    mx = red[0]; __syncthreads();

    float sum = 0.f;
    for (int i = tid; i < NP; i += 128) {
        float e = __expf(p[i] - mx);
        p[i] = e;
        sum += e;
    }
    red[tid] = sum; __syncthreads();
    for (int s = 64; s > 0; s >>= 1) {
        if (tid < s) red[tid] += red[tid + s];
        __syncthreads();
    }
    float inv = 1.f / red[0];
    for (int i = tid; i < NP; i += 128) p[i] *= inv;
}

// ---------------------------------------------------------------------------
extern "C" void kernel_launch(void* const* d_in, const int* in_sizes, int n_in,
                              void* d_out, int out_size)
{
    const float* x     = (const float*)d_in[0];
    const float* Wg    = (const float*)d_in[1];
    const float* bg    = (const float*)d_in[2];
    const float* Wth   = (const float*)d_in[3];
    const float* bth   = (const float*)d_in[4];
    const float* Wph   = (const float*)d_in[5];
    const float* bph   = (const float*)d_in[6];
    const float* Ww    = (const float*)d_in[7];
    const float* bw    = (const float*)d_in[8];
    const float* gamma = (const float*)d_in[9];
    const float* beta  = (const float*)d_in[10];
    const float* rmean = (const float*)d_in[11];
    const float* rvar  = (const float*)d_in[12];
    float* out = (float*)d_out;

    float *xp, *gbuf, *phbuf, *thbuf, *ybuf, *fbuf;
    cudaGetSymbolAddress((void**)&xp,    g_xp);
    cudaGetSymbolAddress((void**)&gbuf,  g_g);
    cudaGetSymbolAddress((void**)&phbuf, g_ph);
    cudaGetSymbolAddress((void**)&thbuf, g_th);
    cudaGetSymbolAddress((void**)&ybuf,  g_y);
    cudaGetSymbolAddress((void**)&fbuf,  g_f);

    cudaFuncSetAttribute(tgemm_kernel<0, true,  false>, cudaFuncAttributeMaxDynamicSharedMemorySize, SM_BYTES);
    cudaFuncSetAttribute(tgemm_kernel<1, false, false>, cudaFuncAttributeMaxDynamicSharedMemorySize, SM_BYTES);
    cudaFuncSetAttribute(tgemm_kernel<2, true,  true >, cudaFuncAttributeMaxDynamicSharedMemorySize, SM_BYTES);
    cudaFuncSetAttribute(tgemm_kernel<3, true,  false>, cudaFuncAttributeMaxDynamicSharedMemorySize, SM_BYTES);

    // 1) maxpool
    {
        long total = (long)BB * CC * NP;
        maxpool_kernel<<<(unsigned)((total + 255) / 256), 256>>>(x);
    }

    // 2) g = Wg @ xp + bg     (M=512, N=1568, K=1024, batch 8)  A k-contig, B n-contig
    {
        dim3 grid((NP + 127) / 128, CI_ / 128, BB);
        tgemm_kernel<0, true, false><<<grid, 256, SM_BYTES>>>(
            Wg, CC, 1, 0,
            xp, NP, 1, (long)CC * NP,
            gbuf, (long)CI_ * NP,
            CI_, NP, CC,
            bg, 0.f, nullptr, nullptr, nullptr, nullptr, nullptr, 0);
    }
    // 3) ph = Wph @ xp + bph
    {
        dim3 grid((NP + 127) / 128, CI_ / 128, BB);
        tgemm_kernel<0, true, false><<<grid, 256, SM_BYTES>>>(
            Wph, CC, 1, 0,
            xp, NP, 1, (long)CC * NP,
            phbuf, (long)CI_ * NP,
            CI_, NP, CC,
            bph, 0.f, nullptr, nullptr, nullptr, nullptr, nullptr, 0);
    }
    // 4) th = Wth @ x + bth   (M=512, N=6272, K=1024, batch 8)
    {
        dim3 grid(NTOT / 128, CI_ / 128, BB);
        tgemm_kernel<0, true, false><<<grid, 256, SM_BYTES>>>(
            Wth, CC, 1, 0,
            x, NTOT, 1, (long)CC * NTOT,
            thbuf, (long)CI_ * NTOT,
            CI_, NTOT, CC,
            bth, 0.f, nullptr, nullptr, nullptr, nullptr, nullptr, 0);
    }
    // 5) f = th^T @ ph * d^-0.5  (M=6272, N=1568, K=256, batch 16)  A m-contig, B n-contig
    {
        dim3 grid((NP + 127) / 128, NTOT / 128, BH);
        tgemm_kernel<1, false, false><<<grid, 256, SM_BYTES>>>(
            thbuf, 1, NTOT, (long)DD * NTOT,
            phbuf, NP, 1, (long)DD * NP,
            fbuf, (long)NTOT * NP,
            NTOT, NP, DD,
            nullptr, 0.0625f, nullptr, nullptr, nullptr, nullptr, nullptr, 0);
    }
    // 6) softmax
    softmax_kernel<<<BH * NTOT, 128>>>(fbuf);

    // 7) y = g @ a^T          (M=256, N=6272, K=1568, batch 16)  A k-contig, B k-contig
    {
        dim3 grid(NTOT / 128, DD / 128, BH);
        tgemm_kernel<2, true, true><<<grid, 256, SM_BYTES>>>(
            gbuf, NP, 1, (long)DD * NP,
            fbuf, 1, NP, (long)NTOT * NP,
            ybuf, (long)DD * NTOT,
            DD, NTOT, NP,
            nullptr, 0.f, nullptr, nullptr, nullptr, nullptr, nullptr, 0);
    }
    // 8) out = BN(Ww @ y + bw) + x   (M=1024, N=6272, K=512, batch 8)
    {
        dim3 grid(NTOT / 128, CC / 128, BB);
        tgemm_kernel<3, true, false><<<grid, 256, SM_BYTES>>>(
            Ww, CI_, 1, 0,
            ybuf, NTOT, 1, (long)CI_ * NTOT,
            out, (long)CC * NTOT,
            CC, NTOT, CI_,
            bw, 0.f, gamma, beta, rmean, rvar, x, (long)CC * NTOT);
    }
}

// round 6
// speedup vs baseline: 3.6642x; 2.1460x over previous
#include <cuda_runtime.h>
#include <math.h>
#include <stdint.h>

// Problem constants
#define BB   8
#define CC   1024
#define CI_  512
#define DD   256
#define TT   8
#define HH   28
#define WW   28
#define NTOT 6272
#define NP   1568
#define BH   16

// Scratch (device globals: allocation-free)
__device__ float g_xp[(long)BB * CC * NP];
__device__ float g_g [(long)BB * CI_ * NP];
__device__ float g_ph[(long)BB * CI_ * NP];
__device__ float g_th[(long)BB * CI_ * NTOT];
__device__ float g_y [(long)BB * CI_ * NTOT];
__device__ float g_f [(long)BH * NTOT * NP];
__device__ float g_xr[(long)BB * CC * NTOT];      // tf32-rounded x (GEMM operand)
__device__ float g_wr[(long)4 * CI_ * CC];        // rounded Wg|Wth|Wph|Ww

__device__ __forceinline__ uint32_t f2tf32(float f) {
    uint32_t r;
    asm("cvt.rna.tf32.f32 %0, %1;" : "=r"(r) : "f"(f));
    return r;
}
__device__ __forceinline__ float tf32f(float f) { return __uint_as_float(f2tf32(f)); }

__device__ __forceinline__ uint32_t smem_u32(const void* p) {
    uint32_t a;
    asm("{ .reg .u64 t; cvta.to.shared.u64 t, %1; cvt.u32.u64 %0, t; }"
        : "=r"(a) : "l"(p));
    return a;
}
__device__ __forceinline__ void cp16(uint32_t dst, const float* src, bool p) {
    int sz = p ? 16 : 0;
    asm volatile("cp.async.cg.shared.global [%0], [%1], 16, %2;"
                 :: "r"(dst), "l"(src), "r"(sz) : "memory");
}
#define CP_COMMIT() asm volatile("cp.async.commit_group;" ::: "memory")
#define CP_WAIT1()  asm volatile("cp.async.wait_group 1;" ::: "memory")

__device__ __forceinline__ void mma16n8k8(float* c, const uint32_t* a, const uint32_t* b) {
    asm volatile(
        "mma.sync.aligned.m16n8k8.row.col.f32.tf32.tf32.f32 "
        "{%0,%1,%2,%3}, {%4,%5,%6,%7}, {%8,%9}, {%0,%1,%2,%3};"
        : "+f"(c[0]), "+f"(c[1]), "+f"(c[2]), "+f"(c[3])
        : "r"(a[0]), "r"(a[1]), "r"(a[2]), "r"(a[3]), "r"(b[0]), "r"(b[1]));
}

// ---------------------------------------------------------------------------
// tf32 rounding convert (n4 float4 elements)
// ---------------------------------------------------------------------------
__global__ void cvt_kernel(const float* __restrict__ in, float* __restrict__ out, long n4) {
    long i = (long)blockIdx.x * blockDim.x + threadIdx.x;
    if (i >= n4) return;
    float4 v = ((const float4*)in)[i];
    float4 o = make_float4(tf32f(v.x), tf32f(v.y), tf32f(v.z), tf32f(v.w));
    ((float4*)out)[i] = o;
}

// ---------------------------------------------------------------------------
// MaxPool3d(1,2,2), output rounded to tf32 (GEMM operand)
// ---------------------------------------------------------------------------
__global__ void maxpool_kernel(const float* __restrict__ x) {
    long idx = (long)blockIdx.x * blockDim.x + threadIdx.x;
    const long total = (long)BB * CC * TT * 14 * 14;
    if (idx >= total) return;
    int ow = idx % 14;
    int oh = (idx / 14) % 14;
    long rest = idx / 196;
    long base = rest * (HH * WW) + (long)(oh * 2) * WW + ow * 2;
    float m0 = fmaxf(x[base], x[base + 1]);
    float m1 = fmaxf(x[base + WW], x[base + WW + 1]);
    g_xp[idx] = tf32f(fmaxf(m0, m1));
}

// ---------------------------------------------------------------------------
// cp.async 3-stage pipelined tf32 mma.sync GEMM.
// C[m,n] = sum_k A'[m*am+k*ak] * B'[k*bk+n*bn]; BM=128, BN=64, BK=32; 8 warps.
// All GEMM operands are pre-rounded to tf32 in gmem (raw copy == cvt.rna).
// AKI: k contig in A -> smem [m][k] stride 36; else [k][m] stride 136.
// BKI: k contig in B -> smem [n][k] stride 36; else [k][n] stride 68.
// EPI: 0=+bias; 1=*scale; 2=plain; 3=BN+residual.  RND: round stores to tf32.
// Requires M%128==0, K%32==0, N%4==0 (N tail bounds-checked).
// ---------------------------------------------------------------------------
#define SM_BYTES 83968

template<int EPI, bool AKI, bool BKI, bool RND>
__global__ void __launch_bounds__(256, 2)
tgemm_kernel(const float* __restrict__ A, long am, long ak, long ab,
             const float* __restrict__ Bp, long bk, long bn, long bb,
             float* __restrict__ Cp, long cb,
             int M, int N, int K,
             const float* __restrict__ bias, float scale,
             const float* __restrict__ gamma, const float* __restrict__ beta,
             const float* __restrict__ rmean, const float* __restrict__ rvar,
             const float* __restrict__ xres, long xb)
{
    extern __shared__ float sm[];
    constexpr int A_WORDS = AKI ? 128 * 36 : 32 * 136;
    constexpr int B_WORDS = BKI ? 64 * 36 : 32 * 68;
    constexpr int STG = A_WORDS + B_WORDS;

    const int tid  = threadIdx.x;
    const int wid  = tid >> 5;
    const int lane = tid & 31;
    const int gq   = lane >> 2;
    const int qq   = lane & 3;
    const int warp_m = (wid & 3) * 32;
    const int warp_n = (wid >> 2) * 32;

    const int bz = blockIdx.z;
    const float* Ab = A  + ab * bz;
    const float* Bb = Bp + bb * bz;
    float*       Cb = Cp + cb * bz;
    const int m0 = blockIdx.y * 128;
    const int n0 = blockIdx.x * 64;

    const uint32_t smb = smem_u32(sm);

    float acc[2][4][4];
#pragma unroll
    for (int i = 0; i < 2; i++)
#pragma unroll
        for (int j = 0; j < 4; j++)
#pragma unroll
            for (int r = 0; r < 4; r++) acc[i][j][r] = 0.f;

    const int KT = K >> 5;

    auto issue = [&](int kt, int s) {
        const int k0 = kt << 5;
        uint32_t sa = smb + (uint32_t)s * (STG * 4);
        uint32_t sb = sa + A_WORDS * 4;
#pragma unroll
        for (int j = 0; j < 4; j++) {
            int e = tid + j * 256;
            if (AKI) {
                int m = e >> 3, kq = e & 7;
                cp16(sa + (m * 36 + kq * 4) * 4,
                     Ab + (long)(m0 + m) * am + (k0 + kq * 4), true);
            } else {
                int mq = e & 31, kk = e >> 5;
                cp16(sa + (kk * 136 + mq * 4) * 4,
                     Ab + (long)(k0 + kk) * ak + (m0 + mq * 4), true);
            }
        }
#pragma unroll
        for (int j = 0; j < 2; j++) {
            int e = tid + j * 256;
            if (BKI) {
                int n = e >> 3, kq = e & 7;
                bool p = (n0 + n) < N;
                int nc = p ? (n0 + n) : (N - 1);
                cp16(sb + (n * 36 + kq * 4) * 4,
                     Bb + (long)nc * bn + (k0 + kq * 4), p);
            } else {
                int nq = e & 15, kk = e >> 4;
                bool p = (n0 + nq * 4) < N;
                int nc = p ? (n0 + nq * 4) : (N - 4);
                cp16(sb + (kk * 68 + nq * 4) * 4,
                     Bb + (long)(k0 + kk) * bk + nc, p);
            }
        }
    };

    auto compute = [&](int s) {
        const uint32_t* pa = (const uint32_t*)(sm + s * STG);
        const uint32_t* pb = pa + A_WORDS;
#pragma unroll
        for (int ks = 0; ks < 4; ks++) {
            const int c = ks * 8 + qq;
            uint32_t afr[2][4];
#pragma unroll
            for (int mf = 0; mf < 2; mf++) {
                int r = warp_m + mf * 16 + gq;
                if (AKI) {
                    afr[mf][0] = pa[r * 36 + c];
                    afr[mf][1] = pa[(r + 8) * 36 + c];
                    afr[mf][2] = pa[r * 36 + c + 4];
                    afr[mf][3] = pa[(r + 8) * 36 + c + 4];
                } else {
                    afr[mf][0] = pa[c * 136 + r];
                    afr[mf][1] = pa[c * 136 + r + 8];
                    afr[mf][2] = pa[(c + 4) * 136 + r];
                    afr[mf][3] = pa[(c + 4) * 136 + r + 8];
                }
            }
#pragma unroll
            for (int nf = 0; nf < 4; nf++) {
                uint32_t bfr[2];
                int n = warp_n + nf * 8 + gq;
                if (BKI) {
                    bfr[0] = pb[n * 36 + c];
                    bfr[1] = pb[n * 36 + c + 4];
                } else {
                    bfr[0] = pb[c * 68 + n];
                    bfr[1] = pb[(c + 4) * 68 + n];
                }
                mma16n8k8(acc[0][nf], afr[0], bfr);
                mma16n8k8(acc[1][nf], afr[1], bfr);
            }
        }
    };

    // prologue: stages 0,1 (uniform two groups)
    issue(0, 0);
    CP_COMMIT();
    if (KT > 1) issue(1, 1);
    CP_COMMIT();

    for (int kt = 0; kt < KT; kt++) {
        CP_WAIT1();
        __syncthreads();
        if (kt + 2 < KT) issue(kt + 2, (kt + 2) % 3);
        CP_COMMIT();
        compute(kt % 3);
    }

    // epilogue
#pragma unroll
    for (int mf = 0; mf < 2; mf++) {
        int r1 = m0 + warp_m + mf * 16 + gq;
        int r2 = r1 + 8;
        float b1 = 0.f, b2 = 0.f, i1 = 0.f, i2 = 0.f, s1 = 0.f, s2 = 0.f;
        if (EPI == 0) { b1 = bias[r1]; b2 = bias[r2]; }
        if (EPI == 3) {
            b1 = bias[r1]; b2 = bias[r2];
            i1 = gamma[r1] * rsqrtf(rvar[r1] + 1e-5f);
            i2 = gamma[r2] * rsqrtf(rvar[r2] + 1e-5f);
            s1 = beta[r1] - rmean[r1] * i1;
            s2 = beta[r2] - rmean[r2] * i2;
        }
#pragma unroll
        for (int nf = 0; nf < 4; nf++) {
            int col = n0 + warp_n + nf * 8 + 2 * qq;
            if (col >= N) continue;
            float v0 = acc[mf][nf][0], v1 = acc[mf][nf][1];
            float v2 = acc[mf][nf][2], v3 = acc[mf][nf][3];
            if (EPI == 0) { v0 += b1; v1 += b1; v2 += b2; v3 += b2; }
            if (EPI == 1) { v0 *= scale; v1 *= scale; v2 *= scale; v3 *= scale; }
            if (EPI == 3) {
                const float* xr = xres + xb * bz;
                float2 x1 = *(const float2*)(xr + (long)r1 * N + col);
                float2 x2 = *(const float2*)(xr + (long)r2 * N + col);
                v0 = (v0 + b1) * i1 + s1 + x1.x;
                v1 = (v1 + b1) * i1 + s1 + x1.y;
                v2 = (v2 + b2) * i2 + s2 + x2.x;
                v3 = (v3 + b2) * i2 + s2 + x2.y;
            }
            if (RND) { v0 = tf32f(v0); v1 = tf32f(v1); v2 = tf32f(v2); v3 = tf32f(v3); }
            *(float2*)(Cb + (long)r1 * N + col) = make_float2(v0, v1);
            *(float2*)(Cb + (long)r2 * N + col) = make_float2(v2, v3);
        }
    }
}

// ---------------------------------------------------------------------------
// Row softmax, in place; output rounded to tf32 (GEMM operand).
// ---------------------------------------------------------------------------
__global__ void softmax_kernel(float* __restrict__ f) {
    float* p = f + (long)blockIdx.x * NP;
    const int tid = threadIdx.x;          // 128 threads
    __shared__ float red[128];

    float mx = -INFINITY;
    for (int i = tid; i < NP; i += 128) mx = fmaxf(mx, p[i]);
    red[tid] = mx; __syncthreads();
    for (int s = 64; s > 0; s >>= 1) {
        if (tid < s) red[tid] = fmaxf(red[tid], red[tid + s]);
        __syncthreads();
    }
    mx = red[0]; __syncthreads();

    float sum = 0.f;
    for (int i = tid; i < NP; i += 128) {
        float e = __expf(p[i] - mx);
        p[i] = e;
        sum += e;
    }
    red[tid] = sum; __syncthreads();
    for (int s = 64; s > 0; s >>= 1) {
        if (tid < s) red[tid] += red[tid + s];
        __syncthreads();
    }
    float inv = 1.f / red[0];
    for (int i = tid; i < NP; i += 128) p[i] = tf32f(p[i] * inv);
}

// ---------------------------------------------------------------------------
extern "C" void kernel_launch(void* const* d_in, const int* in_sizes, int n_in,
                              void* d_out, int out_size)
{
    const float* x     = (const float*)d_in[0];
    const float* Wg    = (const float*)d_in[1];
    const float* bg    = (const float*)d_in[2];
    const float* Wth   = (const float*)d_in[3];
    const float* bth   = (const float*)d_in[4];
    const float* Wph   = (const float*)d_in[5];
    const float* bph   = (const float*)d_in[6];
    const float* Ww    = (const float*)d_in[7];
    const float* bw    = (const float*)d_in[8];
    const float* gamma = (const float*)d_in[9];
    const float* beta  = (const float*)d_in[10];
    const float* rmean = (const float*)d_in[11];
    const float* rvar  = (const float*)d_in[12];
    float* out = (float*)d_out;

    float *xp, *gbuf, *phbuf, *thbuf, *ybuf, *fbuf, *xr, *wr;
    cudaGetSymbolAddress((void**)&xp,    g_xp);
    cudaGetSymbolAddress((void**)&gbuf,  g_g);
    cudaGetSymbolAddress((void**)&phbuf, g_ph);
    cudaGetSymbolAddress((void**)&thbuf, g_th);
    cudaGetSymbolAddress((void**)&ybuf,  g_y);
    cudaGetSymbolAddress((void**)&fbuf,  g_f);
    cudaGetSymbolAddress((void**)&xr,    g_xr);
    cudaGetSymbolAddress((void**)&wr,    g_wr);

    cudaFuncSetAttribute(tgemm_kernel<0, true,  false, true >, cudaFuncAttributeMaxDynamicSharedMemorySize, SM_BYTES);
    cudaFuncSetAttribute(tgemm_kernel<1, false, false, false>, cudaFuncAttributeMaxDynamicSharedMemorySize, SM_BYTES);
    cudaFuncSetAttribute(tgemm_kernel<2, true,  true,  true >, cudaFuncAttributeMaxDynamicSharedMemorySize, SM_BYTES);
    cudaFuncSetAttribute(tgemm_kernel<3, true,  false, false>, cudaFuncAttributeMaxDynamicSharedMemorySize, SM_BYTES);

    const long WSZ = (long)CI_ * CC;   // 524288

    // 0) tf32-round GEMM operands
    {
        long n4 = (long)BB * CC * NTOT / 4;
        cvt_kernel<<<(unsigned)((n4 + 255) / 256), 256>>>(x, xr, n4);
        long w4 = WSZ / 4;
        cvt_kernel<<<(unsigned)((w4 + 255) / 256), 256>>>(Wg,  wr,           w4);
        cvt_kernel<<<(unsigned)((w4 + 255) / 256), 256>>>(Wth, wr + WSZ,     w4);
        cvt_kernel<<<(unsigned)((w4 + 255) / 256), 256>>>(Wph, wr + 2 * WSZ, w4);
        cvt_kernel<<<(unsigned)((w4 + 255) / 256), 256>>>(Ww,  wr + 3 * WSZ, w4);
    }

    // 1) maxpool (rounded)
    {
        long total = (long)BB * CC * NP;
        maxpool_kernel<<<(unsigned)((total + 255) / 256), 256>>>(x);
    }

    // 2) g = Wg @ xp + bg     (M=512, N=1568, K=1024, batch 8)
    {
        dim3 grid((NP + 63) / 64, CI_ / 128, BB);
        tgemm_kernel<0, true, false, true><<<grid, 256, SM_BYTES>>>(
            wr, CC, 1, 0,
            xp, NP, 1, (long)CC * NP,
            gbuf, (long)CI_ * NP,
            CI_, NP, CC,
            bg, 0.f, nullptr, nullptr, nullptr, nullptr, nullptr, 0);
    }
    // 3) ph = Wph @ xp + bph
    {
        dim3 grid((NP + 63) / 64, CI_ / 128, BB);
        tgemm_kernel<0, true, false, true><<<grid, 256, SM_BYTES>>>(
            wr + 2 * WSZ, CC, 1, 0,
            xp, NP, 1, (long)CC * NP,
            phbuf, (long)CI_ * NP,
            CI_, NP, CC,
            bph, 0.f, nullptr, nullptr, nullptr, nullptr, nullptr, 0);
    }
    // 4) th = Wth @ xr + bth  (M=512, N=6272, K=1024, batch 8)
    {
        dim3 grid(NTOT / 64, CI_ / 128, BB);
        tgemm_kernel<0, true, false, true><<<grid, 256, SM_BYTES>>>(
            wr + WSZ, CC, 1, 0,
            xr, NTOT, 1, (long)CC * NTOT,
            thbuf, (long)CI_ * NTOT,
            CI_, NTOT, CC,
            bth, 0.f, nullptr, nullptr, nullptr, nullptr, nullptr, 0);
    }
    // 5) f = th^T @ ph * d^-0.5  (M=6272, N=1568, K=256, batch 16)
    {
        dim3 grid((NP + 63) / 64, NTOT / 128, BH);
        tgemm_kernel<1, false, false, false><<<grid, 256, SM_BYTES>>>(
            thbuf, 1, NTOT, (long)DD * NTOT,
            phbuf, NP, 1, (long)DD * NP,
            fbuf, (long)NTOT * NP,
            NTOT, NP, DD,
            nullptr, 0.0625f, nullptr, nullptr, nullptr, nullptr, nullptr, 0);
    }
    // 6) softmax (rounded)
    softmax_kernel<<<BH * NTOT, 128>>>(fbuf);

    // 7) y = g @ a^T          (M=256, N=6272, K=1568, batch 16)
    {
        dim3 grid(NTOT / 64, DD / 128, BH);
        tgemm_kernel<2, true, true, true><<<grid, 256, SM_BYTES>>>(
            gbuf, NP, 1, (long)DD * NP,
            fbuf, 1, NP, (long)NTOT * NP,
            ybuf, (long)DD * NTOT,
            DD, NTOT, NP,
            nullptr, 0.f, nullptr, nullptr, nullptr, nullptr, nullptr, 0);
    }
    // 8) out = BN(Ww @ y + bw) + x   (M=1024, N=6272, K=512, batch 8)
    {
        dim3 grid(NTOT / 64, CC / 128, BB);
        tgemm_kernel<3, true, false, false><<<grid, 256, SM_BYTES>>>(
            wr + 3 * WSZ, CI_, 1, 0,
            ybuf, NTOT, 1, (long)CI_ * NTOT,
            out, (long)CC * NTOT,
            CC, NTOT, CI_,
            bw, 0.f, gamma, beta, rmean, rvar, x, (long)CC * NTOT);
    }
}

// round 7
// speedup vs baseline: 5.5879x; 1.5250x over previous
#include <cuda_runtime.h>
#include <cuda_bf16.h>
#include <math.h>
#include <stdint.h>

// Problem constants
#define BB   8
#define CC   1024
#define CI_  512
#define DD   256
#define TT   8
#define HH   28
#define WW   28
#define NTOT 6272
#define NP   1568
#define BH   16

// Scratch (device globals: allocation-free), all GEMM operands in bf16
__device__ __nv_bfloat16 b_x [(long)BB * CC * NTOT];
__device__ __nv_bfloat16 b_xp[(long)BB * CC * NP];
__device__ __nv_bfloat16 b_w [(long)4 * CI_ * CC];     // Wg|Wth|Wph|Ww
__device__ __nv_bfloat16 b_g [(long)BB * CI_ * NP];
__device__ __nv_bfloat16 b_ph[(long)BB * CI_ * NP];
__device__ __nv_bfloat16 b_th[(long)BB * CI_ * NTOT];
__device__ __nv_bfloat16 b_y [(long)BB * CI_ * NTOT];
__device__ __nv_bfloat16 b_f [(long)BH * NTOT * NP];

__device__ __forceinline__ uint32_t smem_u32(const void* p) {
    uint32_t a;
    asm("{ .reg .u64 t; cvta.to.shared.u64 t, %1; cvt.u32.u64 %0, t; }"
        : "=r"(a) : "l"(p));
    return a;
}
__device__ __forceinline__ void cp16(uint32_t dst, const void* src, bool p) {
    int sz = p ? 16 : 0;
    asm volatile("cp.async.cg.shared.global [%0], [%1], 16, %2;"
                 :: "r"(dst), "l"(src), "r"(sz) : "memory");
}
#define CP_COMMIT() asm volatile("cp.async.commit_group;" ::: "memory")
#define CP_WAIT1()  asm volatile("cp.async.wait_group 1;" ::: "memory")

__device__ __forceinline__ uint32_t pk(uint16_t lo, uint16_t hi) {
    return (uint32_t)lo | ((uint32_t)hi << 16);
}
__device__ __forceinline__ uint32_t bpack(float a, float b) {
    __nv_bfloat162 t = __floats2bfloat162_rn(a, b);
    return *(uint32_t*)&t;
}

__device__ __forceinline__ void mma_bf16(float* c, const uint32_t* a, const uint32_t* b) {
    asm volatile(
        "mma.sync.aligned.m16n8k16.row.col.f32.bf16.bf16.f32 "
        "{%0,%1,%2,%3}, {%4,%5,%6,%7}, {%8,%9}, {%0,%1,%2,%3};"
        : "+f"(c[0]), "+f"(c[1]), "+f"(c[2]), "+f"(c[3])
        : "r"(a[0]), "r"(a[1]), "r"(a[2]), "r"(a[3]), "r"(b[0]), "r"(b[1]));
}

// ---------------------------------------------------------------------------
// fp32 -> bf16 convert (n4 float4 elements)
// ---------------------------------------------------------------------------
__global__ void cvtb_kernel(const float4* __restrict__ in,
                            __nv_bfloat162* __restrict__ out, long n4) {
    long i = (long)blockIdx.x * blockDim.x + threadIdx.x;
    if (i >= n4) return;
    float4 v = in[i];
    out[2 * i]     = __floats2bfloat162_rn(v.x, v.y);
    out[2 * i + 1] = __floats2bfloat162_rn(v.z, v.w);
}

// ---------------------------------------------------------------------------
// MaxPool3d(1,2,2) -> bf16
// ---------------------------------------------------------------------------
__global__ void maxpool_kernel(const float* __restrict__ x) {
    long idx = (long)blockIdx.x * blockDim.x + threadIdx.x;
    const long total = (long)BB * CC * TT * 14 * 14;
    if (idx >= total) return;
    int ow = idx % 14;
    int oh = (idx / 14) % 14;
    long rest = idx / 196;
    long base = rest * (HH * WW) + (long)(oh * 2) * WW + ow * 2;
    float m0 = fmaxf(x[base], x[base + 1]);
    float m1 = fmaxf(x[base + WW], x[base + WW + 1]);
    b_xp[idx] = __float2bfloat16_rn(fmaxf(m0, m1));
}

// ---------------------------------------------------------------------------
// cp.async 3-stage bf16 mma.sync GEMM (m16n8k16).
// C[m,n] = sum_k A'[m*am+k*ak] * B'[k*bk+n*bn]; BM=128, BN=64, BK=32; 8 warps.
// AKI: k contig in A -> smem [m][k] u32 rows stride 20; else [k][m] bf16 stride 136.
// BKI: k contig in B -> smem [n][k] u32 rows stride 20; else [k][n] bf16 stride 72.
// EPI: 0=+bias->bf16; 1=*scale->bf16; 2=plain->bf16; 3=BN+residual->fp32.
// Requires M%128==0, K%32==0, N%8==0 (N tail zero-filled / bounds-checked).
// ---------------------------------------------------------------------------
#define SM_BYTES 46080

template<int EPI, bool AKI, bool BKI>
__global__ void __launch_bounds__(256, 2)
tgemm_kernel(const __nv_bfloat16* __restrict__ A, long am, long ak, long ab,
             const __nv_bfloat16* __restrict__ Bp, long bk, long bn, long bb,
             void* __restrict__ Cp, long cb,
             int M, int N, int K,
             const float* __restrict__ bias, float scale,
             const float* __restrict__ gamma, const float* __restrict__ beta,
             const float* __restrict__ rmean, const float* __restrict__ rvar,
             const float* __restrict__ xres, long xb)
{
    extern __shared__ char smc[];
    constexpr int A_BYTES = AKI ? 128 * 80 : 32 * 272;   // [m][k]u32 p20 | [k][m]bf16 p136
    constexpr int B_BYTES = BKI ? 64 * 80 : 32 * 144;    // [n][k]u32 p20 | [k][n]bf16 p72
    constexpr int STG_BYTES = A_BYTES + B_BYTES;

    const int tid  = threadIdx.x;
    const int wid  = tid >> 5;
    const int lane = tid & 31;
    const int gq   = lane >> 2;
    const int qq   = lane & 3;
    const int warp_m = (wid & 3) * 32;
    const int warp_n = (wid >> 2) * 32;

    const int bz = blockIdx.z;
    const __nv_bfloat16* Ab = A  + ab * bz;
    const __nv_bfloat16* Bb = Bp + bb * bz;
    const int m0 = blockIdx.y * 128;
    const int n0 = blockIdx.x * 64;

    const uint32_t smb = smem_u32(smc);

    float acc[2][4][4];
#pragma unroll
    for (int i = 0; i < 2; i++)
#pragma unroll
        for (int j = 0; j < 4; j++)
#pragma unroll
            for (int r = 0; r < 4; r++) acc[i][j][r] = 0.f;

    const int KT = K >> 5;

    auto issue = [&](int kt, int s) {
        const int k0 = kt << 5;
        uint32_t sa = smb + (uint32_t)s * STG_BYTES;
        uint32_t sb = sa + A_BYTES;
        if (AKI) {
#pragma unroll
            for (int j = 0; j < 2; j++) {
                int e = tid + j * 256;
                int m = e >> 2, ch = e & 3;
                cp16(sa + m * 80 + ch * 16,
                     Ab + (long)(m0 + m) * am + (k0 + ch * 8), true);
            }
        } else {
#pragma unroll
            for (int j = 0; j < 2; j++) {
                int e = tid + j * 256;
                int kk = e >> 4, ch = e & 15;
                cp16(sa + kk * 272 + ch * 16,
                     Ab + (long)(k0 + kk) * ak + (m0 + ch * 8), true);
            }
        }
        if (BKI) {
            int n = tid >> 2, ch = tid & 3;
            bool p = (n0 + n) < N;
            int nc = p ? (n0 + n) : (N - 1);
            cp16(sb + n * 80 + ch * 16,
                 Bb + (long)nc * bn + (k0 + ch * 8), p);
        } else {
            int kk = tid >> 3, ch = tid & 7;
            bool p = (n0 + ch * 8) < N;
            int nc = p ? (n0 + ch * 8) : (N - 8);
            cp16(sb + kk * 144 + ch * 16,
                 Bb + (long)(k0 + kk) * bk + nc, p);
        }
    };

    auto compute = [&](int s) {
        const char* stg = smc + (size_t)s * STG_BYTES;
        const uint32_t* pa   = (const uint32_t*)stg;
        const uint16_t* pa16 = (const uint16_t*)stg;
        const uint32_t* pb   = (const uint32_t*)(stg + A_BYTES);
        const uint16_t* pb16 = (const uint16_t*)(stg + A_BYTES);
#pragma unroll
        for (int ks = 0; ks < 2; ks++) {
            const int kf = ks * 16 + 2 * qq;
            uint32_t afr[2][4];
#pragma unroll
            for (int mf = 0; mf < 2; mf++) {
                int r = warp_m + mf * 16 + gq;
                if (AKI) {
                    afr[mf][0] = pa[r * 20 + ks * 8 + qq];
                    afr[mf][1] = pa[(r + 8) * 20 + ks * 8 + qq];
                    afr[mf][2] = pa[r * 20 + ks * 8 + qq + 4];
                    afr[mf][3] = pa[(r + 8) * 20 + ks * 8 + qq + 4];
                } else {
                    afr[mf][0] = pk(pa16[kf * 136 + r],       pa16[(kf + 1) * 136 + r]);
                    afr[mf][1] = pk(pa16[kf * 136 + r + 8],   pa16[(kf + 1) * 136 + r + 8]);
                    afr[mf][2] = pk(pa16[(kf + 8) * 136 + r],     pa16[(kf + 9) * 136 + r]);
                    afr[mf][3] = pk(pa16[(kf + 8) * 136 + r + 8], pa16[(kf + 9) * 136 + r + 8]);
                }
            }
#pragma unroll
            for (int nf = 0; nf < 4; nf++) {
                int n = warp_n + nf * 8 + gq;
                uint32_t bfr[2];
                if (BKI) {
                    bfr[0] = pb[n * 20 + ks * 8 + qq];
                    bfr[1] = pb[n * 20 + ks * 8 + qq + 4];
                } else {
                    bfr[0] = pk(pb16[kf * 72 + n],       pb16[(kf + 1) * 72 + n]);
                    bfr[1] = pk(pb16[(kf + 8) * 72 + n], pb16[(kf + 9) * 72 + n]);
                }
                mma_bf16(acc[0][nf], afr[0], bfr);
                mma_bf16(acc[1][nf], afr[1], bfr);
            }
        }
    };

    // prologue
    issue(0, 0);
    CP_COMMIT();
    if (KT > 1) issue(1, 1);
    CP_COMMIT();

    for (int kt = 0; kt < KT; kt++) {
        CP_WAIT1();
        __syncthreads();
        if (kt + 2 < KT) issue(kt + 2, (kt + 2) % 3);
        CP_COMMIT();
        compute(kt % 3);
    }

    // epilogue
    if (EPI == 3) {
        float* Cb = (float*)Cp + cb * bz;
#pragma unroll
        for (int mf = 0; mf < 2; mf++) {
            int r1 = m0 + warp_m + mf * 16 + gq;
            int r2 = r1 + 8;
            float b1 = bias[r1], b2 = bias[r2];
            float i1 = gamma[r1] * rsqrtf(rvar[r1] + 1e-5f);
            float i2 = gamma[r2] * rsqrtf(rvar[r2] + 1e-5f);
            float s1 = beta[r1] - rmean[r1] * i1;
            float s2 = beta[r2] - rmean[r2] * i2;
#pragma unroll
            for (int nf = 0; nf < 4; nf++) {
                int col = n0 + warp_n + nf * 8 + 2 * qq;
                if (col >= N) continue;
                const float* xr = xres + xb * bz;
                float2 x1 = *(const float2*)(xr + (long)r1 * N + col);
                float2 x2 = *(const float2*)(xr + (long)r2 * N + col);
                float v0 = (acc[mf][nf][0] + b1) * i1 + s1 + x1.x;
                float v1 = (acc[mf][nf][1] + b1) * i1 + s1 + x1.y;
                float v2 = (acc[mf][nf][2] + b2) * i2 + s2 + x2.x;
                float v3 = (acc[mf][nf][3] + b2) * i2 + s2 + x2.y;
                *(float2*)(Cb + (long)r1 * N + col) = make_float2(v0, v1);
                *(float2*)(Cb + (long)r2 * N + col) = make_float2(v2, v3);
            }
        }
    } else {
        __nv_bfloat16* Cb = (__nv_bfloat16*)Cp + cb * bz;
#pragma unroll
        for (int mf = 0; mf < 2; mf++) {
            int r1 = m0 + warp_m + mf * 16 + gq;
            int r2 = r1 + 8;
            float b1 = 0.f, b2 = 0.f;
            if (EPI == 0) { b1 = bias[r1]; b2 = bias[r2]; }
#pragma unroll
            for (int nf = 0; nf < 4; nf++) {
                int col = n0 + warp_n + nf * 8 + 2 * qq;
                if (col >= N) continue;
                float v0 = acc[mf][nf][0], v1 = acc[mf][nf][1];
                float v2 = acc[mf][nf][2], v3 = acc[mf][nf][3];
                if (EPI == 0) { v0 += b1; v1 += b1; v2 += b2; v3 += b2; }
                if (EPI == 1) { v0 *= scale; v1 *= scale; v2 *= scale; v3 *= scale; }
                *(uint32_t*)(Cb + (long)r1 * N + col) = bpack(v0, v1);
                *(uint32_t*)(Cb + (long)r2 * N + col) = bpack(v2, v3);
            }
        }
    }
}

// ---------------------------------------------------------------------------
// Row softmax, in place on bf16 rows of width NP (pairs of 2).
// ---------------------------------------------------------------------------
__global__ void softmax_kernel(__nv_bfloat162* __restrict__ f) {
    __nv_bfloat162* p = f + (long)blockIdx.x * (NP / 2);
    const int tid = threadIdx.x;          // 128 threads
    __shared__ float red[128];

    float mx = -INFINITY;
    for (int i = tid; i < NP / 2; i += 128) {
        float2 v = __bfloat1622float2(p[i]);
        mx = fmaxf(mx, fmaxf(v.x, v.y));
    }
    red[tid] = mx; __syncthreads();
    for (int s = 64; s > 0; s >>= 1) {
        if (tid < s) red[tid] = fmaxf(red[tid], red[tid + s]);
        __syncthreads();
    }
    mx = red[0]; __syncthreads();

    float sum = 0.f;
    for (int i = tid; i < NP / 2; i += 128) {
        float2 v = __bfloat1622float2(p[i]);
        float e0 = __expf(v.x - mx);
        float e1 = __expf(v.y - mx);
        p[i] = __floats2bfloat162_rn(e0, e1);
        sum += e0 + e1;
    }
    red[tid] = sum; __syncthreads();
    for (int s = 64; s > 0; s >>= 1) {
        if (tid < s) red[tid] += red[tid + s];
        __syncthreads();
    }
    float inv = 1.f / red[0];
    for (int i = tid; i < NP / 2; i += 128) {
        float2 v = __bfloat1622float2(p[i]);
        p[i] = __floats2bfloat162_rn(v.x * inv, v.y * inv);
    }
}

// ---------------------------------------------------------------------------
extern "C" void kernel_launch(void* const* d_in, const int* in_sizes, int n_in,
                              void* d_out, int out_size)
{
    const float* x     = (const float*)d_in[0];
    const float* Wg    = (const float*)d_in[1];
    const float* bg    = (const float*)d_in[2];
    const float* Wth   = (const float*)d_in[3];
    const float* bth   = (const float*)d_in[4];
    const float* Wph   = (const float*)d_in[5];
    const float* bph   = (const float*)d_in[6];
    const float* Ww    = (const float*)d_in[7];
    const float* bw    = (const float*)d_in[8];
    const float* gamma = (const float*)d_in[9];
    const float* beta  = (const float*)d_in[10];
    const float* rmean = (const float*)d_in[11];
    const float* rvar  = (const float*)d_in[12];
    float* out = (float*)d_out;

    __nv_bfloat16 *xb, *xpb, *wb, *gb, *phb, *thb, *yb, *fb;
    cudaGetSymbolAddress((void**)&xb,  b_x);
    cudaGetSymbolAddress((void**)&xpb, b_xp);
    cudaGetSymbolAddress((void**)&wb,  b_w);
    cudaGetSymbolAddress((void**)&gb,  b_g);
    cudaGetSymbolAddress((void**)&phb, b_ph);
    cudaGetSymbolAddress((void**)&thb, b_th);
    cudaGetSymbolAddress((void**)&yb,  b_y);
    cudaGetSymbolAddress((void**)&fb,  b_f);

    cudaFuncSetAttribute(tgemm_kernel<0, true,  false>, cudaFuncAttributeMaxDynamicSharedMemorySize, SM_BYTES);
    cudaFuncSetAttribute(tgemm_kernel<1, false, false>, cudaFuncAttributeMaxDynamicSharedMemorySize, SM_BYTES);
    cudaFuncSetAttribute(tgemm_kernel<2, true,  true >, cudaFuncAttributeMaxDynamicSharedMemorySize, SM_BYTES);
    cudaFuncSetAttribute(tgemm_kernel<3, true,  false>, cudaFuncAttributeMaxDynamicSharedMemorySize, SM_BYTES);

    const long WSZ = (long)CI_ * CC;   // 524288

    // 0) bf16 operand conversion
    {
        long n4 = (long)BB * CC * NTOT / 4;
        cvtb_kernel<<<(unsigned)((n4 + 255) / 256), 256>>>(
            (const float4*)x, (__nv_bfloat162*)xb, n4);
        long w4 = WSZ / 4;
        cvtb_kernel<<<(unsigned)((w4 + 255) / 256), 256>>>((const float4*)Wg,  (__nv_bfloat162*)(wb),           w4);
        cvtb_kernel<<<(unsigned)((w4 + 255) / 256), 256>>>((const float4*)Wth, (__nv_bfloat162*)(wb + WSZ),     w4);
        cvtb_kernel<<<(unsigned)((w4 + 255) / 256), 256>>>((const float4*)Wph, (__nv_bfloat162*)(wb + 2 * WSZ), w4);
        cvtb_kernel<<<(unsigned)((w4 + 255) / 256), 256>>>((const float4*)Ww,  (__nv_bfloat162*)(wb + 3 * WSZ), w4);
    }

    // 1) maxpool -> bf16
    {
        long total = (long)BB * CC * NP;
        maxpool_kernel<<<(unsigned)((total + 255) / 256), 256>>>(x);
    }

    // 2) g = Wg @ xp + bg     (M=512, N=1568, K=1024, batch 8)
    {
        dim3 grid((NP + 63) / 64, CI_ / 128, BB);
        tgemm_kernel<0, true, false><<<grid, 256, SM_BYTES>>>(
            wb, CC, 1, 0,
            xpb, NP, 1, (long)CC * NP,
            gb, (long)CI_ * NP,
            CI_, NP, CC,
            bg, 0.f, nullptr, nullptr, nullptr, nullptr, nullptr, 0);
    }
    // 3) ph = Wph @ xp + bph
    {
        dim3 grid((NP + 63) / 64, CI_ / 128, BB);
        tgemm_kernel<0, true, false><<<grid, 256, SM_BYTES>>>(
            wb + 2 * WSZ, CC, 1, 0,
            xpb, NP, 1, (long)CC * NP,
            phb, (long)CI_ * NP,
            CI_, NP, CC,
            bph, 0.f, nullptr, nullptr, nullptr, nullptr, nullptr, 0);
    }
    // 4) th = Wth @ x + bth   (M=512, N=6272, K=1024, batch 8)
    {
        dim3 grid(NTOT / 64, CI_ / 128, BB);
        tgemm_kernel<0, true, false><<<grid, 256, SM_BYTES>>>(
            wb + WSZ, CC, 1, 0,
            xb, NTOT, 1, (long)CC * NTOT,
            thb, (long)CI_ * NTOT,
            CI_, NTOT, CC,
            bth, 0.f, nullptr, nullptr, nullptr, nullptr, nullptr, 0);
    }
    // 5) f = th^T @ ph * d^-0.5  (M=6272, N=1568, K=256, batch 16)
    {
        dim3 grid((NP + 63) / 64, NTOT / 128, BH);
        tgemm_kernel<1, false, false><<<grid, 256, SM_BYTES>>>(
            thb, 1, NTOT, (long)DD * NTOT,
            phb, NP, 1, (long)DD * NP,
            fb, (long)NTOT * NP,
            NTOT, NP, DD,
            nullptr, 0.0625f, nullptr, nullptr, nullptr, nullptr, nullptr, 0);
    }
    // 6) softmax
    softmax_kernel<<<BH * NTOT, 128>>>((__nv_bfloat162*)fb);

    // 7) y = g @ a^T          (M=256, N=6272, K=1568, batch 16)
    {
        dim3 grid(NTOT / 64, DD / 128, BH);
        tgemm_kernel<2, true, true><<<grid, 256, SM_BYTES>>>(
            gb, NP, 1, (long)DD * NP,
            fb, 1, NP, (long)NTOT * NP,
            yb, (long)DD * NTOT,
            DD, NTOT, NP,
            nullptr, 0.f, nullptr, nullptr, nullptr, nullptr, nullptr, 0);
    }
    // 8) out = BN(Ww @ y + bw) + x   (M=1024, N=6272, K=512, batch 8)
    {
        dim3 grid(NTOT / 64, CC / 128, BB);
        tgemm_kernel<3, true, false><<<grid, 256, SM_BYTES>>>(
            wb + 3 * WSZ, CI_, 1, 0,
            yb, NTOT, 1, (long)CI_ * NTOT,
            out, (long)CC * NTOT,
            CC, NTOT, CI_,
            bw, 0.f, gamma, beta, rmean, rvar, x, (long)CC * NTOT);
    }
}

// round 8
// speedup vs baseline: 7.2670x; 1.3005x over previous
#include <cuda_runtime.h>
#include <cuda_bf16.h>
#include <math.h>
#include <stdint.h>

// Problem constants
#define BB   8
#define CC   1024
#define CI_  512
#define DD   256
#define TT   8
#define HH   28
#define WW   28
#define NTOT 6272
#define NP   1568
#define BH   16

// Scratch (device globals: allocation-free), all GEMM operands in bf16
__device__ __nv_bfloat16 b_x [(long)BB * CC * NTOT];
__device__ __nv_bfloat16 b_xp[(long)BB * CC * NP];
__device__ __nv_bfloat16 b_w [(long)4 * CI_ * CC];     // Wg|Wth|Wph|Ww
__device__ __nv_bfloat16 b_g [(long)BB * CI_ * NP];
__device__ __nv_bfloat16 b_ph[(long)BB * CI_ * NP];
__device__ __nv_bfloat16 b_th[(long)BB * CI_ * NTOT];
__device__ __nv_bfloat16 b_y [(long)BB * CI_ * NTOT];
__device__ __nv_bfloat16 b_f [(long)BH * NTOT * NP];

__device__ __forceinline__ uint32_t smem_u32(const void* p) {
    uint32_t a;
    asm("{ .reg .u64 t; cvta.to.shared.u64 t, %1; cvt.u32.u64 %0, t; }"
        : "=r"(a) : "l"(p));
    return a;
}
__device__ __forceinline__ void cp16(uint32_t dst, const void* src, bool p) {
    int sz = p ? 16 : 0;
    asm volatile("cp.async.cg.shared.global [%0], [%1], 16, %2;"
                 :: "r"(dst), "l"(src), "r"(sz) : "memory");
}
#define CP_COMMIT() asm volatile("cp.async.commit_group;" ::: "memory")
#define CP_WAIT1()  asm volatile("cp.async.wait_group 1;" ::: "memory")

__device__ __forceinline__ uint32_t pk(uint16_t lo, uint16_t hi) {
    return (uint32_t)lo | ((uint32_t)hi << 16);
}
__device__ __forceinline__ uint32_t bpack(float a, float b) {
    __nv_bfloat162 t = __floats2bfloat162_rn(a, b);
    return *(uint32_t*)&t;
}

__device__ __forceinline__ void mma_bf16(float* c, const uint32_t* a, const uint32_t* b) {
    asm volatile(
        "mma.sync.aligned.m16n8k16.row.col.f32.bf16.bf16.f32 "
        "{%0,%1,%2,%3}, {%4,%5,%6,%7}, {%8,%9}, {%0,%1,%2,%3};"
        : "+f"(c[0]), "+f"(c[1]), "+f"(c[2]), "+f"(c[3])
        : "r"(a[0]), "r"(a[1]), "r"(a[2]), "r"(a[3]), "r"(b[0]), "r"(b[1]));
}

// ---------------------------------------------------------------------------
// fp32 -> bf16 convert (n4 float4 elements)
// ---------------------------------------------------------------------------
__global__ void cvtb_kernel(const float4* __restrict__ in,
                            __nv_bfloat162* __restrict__ out, long n4) {
    long i = (long)blockIdx.x * blockDim.x + threadIdx.x;
    if (i >= n4) return;
    float4 v = in[i];
    out[2 * i]     = __floats2bfloat162_rn(v.x, v.y);
    out[2 * i + 1] = __floats2bfloat162_rn(v.z, v.w);
}

// ---------------------------------------------------------------------------
// MaxPool3d(1,2,2) -> bf16
// ---------------------------------------------------------------------------
__global__ void maxpool_kernel(const float* __restrict__ x) {
    long idx = (long)blockIdx.x * blockDim.x + threadIdx.x;
    const long total = (long)BB * CC * TT * 14 * 14;
    if (idx >= total) return;
    int ow = idx % 14;
    int oh = (idx / 14) % 14;
    long rest = idx / 196;
    long base = rest * (HH * WW) + (long)(oh * 2) * WW + ow * 2;
    float m0 = fmaxf(x[base], x[base + 1]);
    float m1 = fmaxf(x[base + WW], x[base + WW + 1]);
    b_xp[idx] = __float2bfloat16_rn(fmaxf(m0, m1));
}

// ---------------------------------------------------------------------------
// cp.async 3-stage bf16 mma.sync GEMM (m16n8k16).
// C[m,n] = sum_k A'[m*am+k*ak] * B'[k*bk+n*bn]; BM=128, BN=128, BK=32; 8 warps
// (warp grid 4m x 2n, warp tile 32x64).
// AKI: k contig in A -> smem [m][k] u32 stride 20; else [k][m] bf16 stride 136.
// BKI: k contig in B -> smem [n][k] u32 stride 20; else [k][n] bf16 stride 136.
// EPI: 0=+bias->bf16; 1=*scale->bf16; 2=plain->bf16; 3=BN+residual->fp32.
// Requires M%128==0, K%32==0, N%8==0 (N tail bounds-checked).
// ---------------------------------------------------------------------------
#define SM_BYTES 61440

template<int EPI, bool AKI, bool BKI>
__global__ void __launch_bounds__(256, 2)
tgemm_kernel(const __nv_bfloat16* __restrict__ A, long am, long ak, long ab,
             const __nv_bfloat16* __restrict__ Bp, long bk, long bn, long bb,
             void* __restrict__ Cp, long cb,
             int M, int N, int K,
             const float* __restrict__ bias, float scale,
             const float* __restrict__ gamma, const float* __restrict__ beta,
             const float* __restrict__ rmean, const float* __restrict__ rvar,
             const float* __restrict__ xres, long xb)
{
    extern __shared__ char smc[];
    constexpr int A_BYTES = AKI ? 128 * 80 : 32 * 272;
    constexpr int B_BYTES = BKI ? 128 * 80 : 32 * 272;
    constexpr int STG_BYTES = A_BYTES + B_BYTES;

    const int tid  = threadIdx.x;
    const int wid  = tid >> 5;
    const int lane = tid & 31;
    const int gq   = lane >> 2;
    const int qq   = lane & 3;
    const int warp_m = (wid & 3) * 32;
    const int warp_n = (wid >> 2) * 64;

    const int bz = blockIdx.z;
    const __nv_bfloat16* Ab = A  + ab * bz;
    const __nv_bfloat16* Bb = Bp + bb * bz;
    const int m0 = blockIdx.y * 128;
    const int n0 = blockIdx.x * 128;

    const uint32_t smb = smem_u32(smc);

    float acc[2][8][4];
#pragma unroll
    for (int i = 0; i < 2; i++)
#pragma unroll
        for (int j = 0; j < 8; j++)
#pragma unroll
            for (int r = 0; r < 4; r++) acc[i][j][r] = 0.f;

    const int KT = K >> 5;

    auto issue = [&](int kt, int s) {
        const int k0 = kt << 5;
        uint32_t sa = smb + (uint32_t)s * STG_BYTES;
        uint32_t sb = sa + A_BYTES;
#pragma unroll
        for (int j = 0; j < 2; j++) {
            int e = tid + j * 256;
            if (AKI) {
                int m = e >> 2, ch = e & 3;
                cp16(sa + m * 80 + ch * 16,
                     Ab + (long)(m0 + m) * am + (k0 + ch * 8), true);
            } else {
                int kk = e >> 4, ch = e & 15;
                cp16(sa + kk * 272 + ch * 16,
                     Ab + (long)(k0 + kk) * ak + (m0 + ch * 8), true);
            }
        }
#pragma unroll
        for (int j = 0; j < 2; j++) {
            int e = tid + j * 256;
            if (BKI) {
                int n = e >> 2, ch = e & 3;
                bool p = (n0 + n) < N;
                int nc = p ? (n0 + n) : (N - 1);
                cp16(sb + n * 80 + ch * 16,
                     Bb + (long)nc * bn + (k0 + ch * 8), p);
            } else {
                int kk = e >> 4, ch = e & 15;
                bool p = (n0 + ch * 8) < N;
                int nc = p ? (n0 + ch * 8) : (N - 8);
                cp16(sb + kk * 272 + ch * 16,
                     Bb + (long)(k0 + kk) * bk + nc, p);
            }
        }
    };

    auto compute = [&](int s) {
        const char* stg = smc + (size_t)s * STG_BYTES;
        const uint32_t* pa   = (const uint32_t*)stg;
        const uint16_t* pa16 = (const uint16_t*)stg;
        const uint32_t* pb   = (const uint32_t*)(stg + A_BYTES);
        const uint16_t* pb16 = (const uint16_t*)(stg + A_BYTES);
#pragma unroll
        for (int ks = 0; ks < 2; ks++) {
            const int kf = ks * 16 + 2 * qq;
            uint32_t afr[2][4];
#pragma unroll
            for (int mf = 0; mf < 2; mf++) {
                int r = warp_m + mf * 16 + gq;
                if (AKI) {
                    afr[mf][0] = pa[r * 20 + ks * 8 + qq];
                    afr[mf][1] = pa[(r + 8) * 20 + ks * 8 + qq];
                    afr[mf][2] = pa[r * 20 + ks * 8 + qq + 4];
                    afr[mf][3] = pa[(r + 8) * 20 + ks * 8 + qq + 4];
                } else {
                    afr[mf][0] = pk(pa16[kf * 136 + r],       pa16[(kf + 1) * 136 + r]);
                    afr[mf][1] = pk(pa16[kf * 136 + r + 8],   pa16[(kf + 1) * 136 + r + 8]);
                    afr[mf][2] = pk(pa16[(kf + 8) * 136 + r],     pa16[(kf + 9) * 136 + r]);
                    afr[mf][3] = pk(pa16[(kf + 8) * 136 + r + 8], pa16[(kf + 9) * 136 + r + 8]);
                }
            }
#pragma unroll
            for (int nf = 0; nf < 8; nf++) {
                int n = warp_n + nf * 8 + gq;
                uint32_t bfr[2];
                if (BKI) {
                    bfr[0] = pb[n * 20 + ks * 8 + qq];
                    bfr[1] = pb[n * 20 + ks * 8 + qq + 4];
                } else {
                    bfr[0] = pk(pb16[kf * 136 + n],       pb16[(kf + 1) * 136 + n]);
                    bfr[1] = pk(pb16[(kf + 8) * 136 + n], pb16[(kf + 9) * 136 + n]);
                }
                mma_bf16(acc[0][nf], afr[0], bfr);
                mma_bf16(acc[1][nf], afr[1], bfr);
            }
        }
    };

    // prologue
    issue(0, 0);
    CP_COMMIT();
    if (KT > 1) issue(1, 1);
    CP_COMMIT();

    for (int kt = 0; kt < KT; kt++) {
        CP_WAIT1();
        __syncthreads();
        if (kt + 2 < KT) issue(kt + 2, (kt + 2) % 3);
        CP_COMMIT();
        compute(kt % 3);
    }

    // epilogue
    if (EPI == 3) {
        float* Cb = (float*)Cp + cb * bz;
#pragma unroll
        for (int mf = 0; mf < 2; mf++) {
            int r1 = m0 + warp_m + mf * 16 + gq;
            int r2 = r1 + 8;
            float b1 = bias[r1], b2 = bias[r2];
            float i1 = gamma[r1] * rsqrtf(rvar[r1] + 1e-5f);
            float i2 = gamma[r2] * rsqrtf(rvar[r2] + 1e-5f);
            float s1 = beta[r1] - rmean[r1] * i1;
            float s2 = beta[r2] - rmean[r2] * i2;
#pragma unroll
            for (int nf = 0; nf < 8; nf++) {
                int col = n0 + warp_n + nf * 8 + 2 * qq;
                if (col >= N) continue;
                const float* xr = xres + xb * bz;
                float2 x1 = *(const float2*)(xr + (long)r1 * N + col);
                float2 x2 = *(const float2*)(xr + (long)r2 * N + col);
                float v0 = (acc[mf][nf][0] + b1) * i1 + s1 + x1.x;
                float v1 = (acc[mf][nf][1] + b1) * i1 + s1 + x1.y;
                float v2 = (acc[mf][nf][2] + b2) * i2 + s2 + x2.x;
                float v3 = (acc[mf][nf][3] + b2) * i2 + s2 + x2.y;
                *(float2*)(Cb + (long)r1 * N + col) = make_float2(v0, v1);
                *(float2*)(Cb + (long)r2 * N + col) = make_float2(v2, v3);
            }
        }
    } else {
        __nv_bfloat16* Cb = (__nv_bfloat16*)Cp + cb * bz;
#pragma unroll
        for (int mf = 0; mf < 2; mf++) {
            int r1 = m0 + warp_m + mf * 16 + gq;
            int r2 = r1 + 8;
            float b1 = 0.f, b2 = 0.f;
            if (EPI == 0) { b1 = bias[r1]; b2 = bias[r2]; }
#pragma unroll
            for (int nf = 0; nf < 8; nf++) {
                int col = n0 + warp_n + nf * 8 + 2 * qq;
                if (col >= N) continue;
                float v0 = acc[mf][nf][0], v1 = acc[mf][nf][1];
                float v2 = acc[mf][nf][2], v3 = acc[mf][nf][3];
                if (EPI == 0) { v0 += b1; v1 += b1; v2 += b2; v3 += b2; }
                if (EPI == 1) { v0 *= scale; v1 *= scale; v2 *= scale; v3 *= scale; }
                *(uint32_t*)(Cb + (long)r1 * N + col) = bpack(v0, v1);
                *(uint32_t*)(Cb + (long)r2 * N + col) = bpack(v2, v3);
            }
        }
    }
}

// ---------------------------------------------------------------------------
// Single-pass row softmax on bf16 rows of width NP. One read + one write.
// Numerics identical to the 3-pass version: sum accumulates UNROUNDED exps,
// stored value = bf16(bf16(e) * inv).
// ---------------------------------------------------------------------------
__global__ void softmax_kernel(__nv_bfloat162* __restrict__ f) {
    __nv_bfloat162* p = f + (long)blockIdx.x * (NP / 2);
    const int tid = threadIdx.x;          // 128 threads
    __shared__ float red[128];

    // NP/2 = 784 = 6*128 + 16
    uint32_t v[7];
    const bool has7 = (tid < 16);

#pragma unroll
    for (int j = 0; j < 7; j++) {
        int i = tid + j * 128;
        if (j < 6 || has7) v[j] = *(uint32_t*)&p[i];
    }

    float mx = -INFINITY;
#pragma unroll
    for (int j = 0; j < 7; j++) {
        if (j < 6 || has7) {
            float2 t = __bfloat1622float2(*(__nv_bfloat162*)&v[j]);
            mx = fmaxf(mx, fmaxf(t.x, t.y));
        }
    }
    red[tid] = mx; __syncthreads();
    for (int s = 64; s > 0; s >>= 1) {
        if (tid < s) red[tid] = fmaxf(red[tid], red[tid + s]);
        __syncthreads();
    }
    mx = red[0]; __syncthreads();

    float sum = 0.f;
#pragma unroll
    for (int j = 0; j < 7; j++) {
        if (j < 6 || has7) {
            float2 t = __bfloat1622float2(*(__nv_bfloat162*)&v[j]);
            float e0 = __expf(t.x - mx);
            float e1 = __expf(t.y - mx);
            sum += e0 + e1;
            v[j] = bpack(e0, e1);
        }
    }
    red[tid] = sum; __syncthreads();
    for (int s = 64; s > 0; s >>= 1) {
        if (tid < s) red[tid] += red[tid + s];
        __syncthreads();
    }
    float inv = 1.f / red[0];

#pragma unroll
    for (int j = 0; j < 7; j++) {
        int i = tid + j * 128;
        if (j < 6 || has7) {
            float2 t = __bfloat1622float2(*(__nv_bfloat162*)&v[j]);
            uint32_t o = bpack(t.x * inv, t.y * inv);
            *(uint32_t*)&p[i] = o;
        }
    }
}

// ---------------------------------------------------------------------------
extern "C" void kernel_launch(void* const* d_in, const int* in_sizes, int n_in,
                              void* d_out, int out_size)
{
    const float* x     = (const float*)d_in[0];
    const float* Wg    = (const float*)d_in[1];
    const float* bg    = (const float*)d_in[2];
    const float* Wth   = (const float*)d_in[3];
    const float* bth   = (const float*)d_in[4];
    const float* Wph   = (const float*)d_in[5];
    const float* bph   = (const float*)d_in[6];
    const float* Ww    = (const float*)d_in[7];
    const float* bw    = (const float*)d_in[8];
    const float* gamma = (const float*)d_in[9];
    const float* beta  = (const float*)d_in[10];
    const float* rmean = (const float*)d_in[11];
    const float* rvar  = (const float*)d_in[12];
    float* out = (float*)d_out;

    __nv_bfloat16 *xb, *xpb, *wb, *gb, *phb, *thb, *yb, *fb;
    cudaGetSymbolAddress((void**)&xb,  b_x);
    cudaGetSymbolAddress((void**)&xpb, b_xp);
    cudaGetSymbolAddress((void**)&wb,  b_w);
    cudaGetSymbolAddress((void**)&gb,  b_g);
    cudaGetSymbolAddress((void**)&phb, b_ph);
    cudaGetSymbolAddress((void**)&thb, b_th);
    cudaGetSymbolAddress((void**)&yb,  b_y);
    cudaGetSymbolAddress((void**)&fb,  b_f);

    cudaFuncSetAttribute(tgemm_kernel<0, true,  false>, cudaFuncAttributeMaxDynamicSharedMemorySize, SM_BYTES);
    cudaFuncSetAttribute(tgemm_kernel<1, false, false>, cudaFuncAttributeMaxDynamicSharedMemorySize, SM_BYTES);
    cudaFuncSetAttribute(tgemm_kernel<2, true,  true >, cudaFuncAttributeMaxDynamicSharedMemorySize, SM_BYTES);
    cudaFuncSetAttribute(tgemm_kernel<3, true,  false>, cudaFuncAttributeMaxDynamicSharedMemorySize, SM_BYTES);

    const long WSZ = (long)CI_ * CC;   // 524288

    // 0) bf16 operand conversion
    {
        long n4 = (long)BB * CC * NTOT / 4;
        cvtb_kernel<<<(unsigned)((n4 + 255) / 256), 256>>>(
            (const float4*)x, (__nv_bfloat162*)xb, n4);
        long w4 = WSZ / 4;
        cvtb_kernel<<<(unsigned)((w4 + 255) / 256), 256>>>((const float4*)Wg,  (__nv_bfloat162*)(wb),           w4);
        cvtb_kernel<<<(unsigned)((w4 + 255) / 256), 256>>>((const float4*)Wth, (__nv_bfloat162*)(wb + WSZ),     w4);
        cvtb_kernel<<<(unsigned)((w4 + 255) / 256), 256>>>((const float4*)Wph, (__nv_bfloat162*)(wb + 2 * WSZ), w4);
        cvtb_kernel<<<(unsigned)((w4 + 255) / 256), 256>>>((const float4*)Ww,  (__nv_bfloat162*)(wb + 3 * WSZ), w4);
    }

    // 1) maxpool -> bf16
    {
        long total = (long)BB * CC * NP;
        maxpool_kernel<<<(unsigned)((total + 255) / 256), 256>>>(x);
    }

    // 2) g = Wg @ xp + bg     (M=512, N=1568, K=1024, batch 8)
    {
        dim3 grid((NP + 127) / 128, CI_ / 128, BB);
        tgemm_kernel<0, true, false><<<grid, 256, SM_BYTES>>>(
            wb, CC, 1, 0,
            xpb, NP, 1, (long)CC * NP,
            gb, (long)CI_ * NP,
            CI_, NP, CC,
            bg, 0.f, nullptr, nullptr, nullptr, nullptr, nullptr, 0);
    }
    // 3) ph = Wph @ xp + bph
    {
        dim3 grid((NP + 127) / 128, CI_ / 128, BB);
        tgemm_kernel<0, true, false><<<grid, 256, SM_BYTES>>>(
            wb + 2 * WSZ, CC, 1, 0,
            xpb, NP, 1, (long)CC * NP,
            phb, (long)CI_ * NP,
            CI_, NP, CC,
            bph, 0.f, nullptr, nullptr, nullptr, nullptr, nullptr, 0);
    }
    // 4) th = Wth @ x + bth   (M=512, N=6272, K=1024, batch 8)
    {
        dim3 grid(NTOT / 128, CI_ / 128, BB);
        tgemm_kernel<0, true, false><<<grid, 256, SM_BYTES>>>(
            wb + WSZ, CC, 1, 0,
            xb, NTOT, 1, (long)CC * NTOT,
            thb, (long)CI_ * NTOT,
            CI_, NTOT, CC,
            bth, 0.f, nullptr, nullptr, nullptr, nullptr, nullptr, 0);
    }
    // 5) f = th^T @ ph * d^-0.5  (M=6272, N=1568, K=256, batch 16)
    {
        dim3 grid((NP + 127) / 128, NTOT / 128, BH);
        tgemm_kernel<1, false, false><<<grid, 256, SM_BYTES>>>(
            thb, 1, NTOT, (long)DD * NTOT,
            phb, NP, 1, (long)DD * NP,
            fb, (long)NTOT * NP,
            NTOT, NP, DD,
            nullptr, 0.0625f, nullptr, nullptr, nullptr, nullptr, nullptr, 0);
    }
    // 6) softmax (single-pass)
    softmax_kernel<<<BH * NTOT, 128>>>((__nv_bfloat162*)fb);

    // 7) y = g @ a^T          (M=256, N=6272, K=1568, batch 16)
    {
        dim3 grid(NTOT / 128, DD / 128, BH);
        tgemm_kernel<2, true, true><<<grid, 256, SM_BYTES>>>(
            gb, NP, 1, (long)DD * NP,
            fb, 1, NP, (long)NTOT * NP,
            yb, (long)DD * NTOT,
            DD, NTOT, NP,
            nullptr, 0.f, nullptr, nullptr, nullptr, nullptr, nullptr, 0);
    }
    // 8) out = BN(Ww @ y + bw) + x   (M=1024, N=6272, K=512, batch 8)
    {
        dim3 grid(NTOT / 128, CC / 128, BB);
        tgemm_kernel<3, true, false><<<grid, 256, SM_BYTES>>>(
            wb + 3 * WSZ, CI_, 1, 0,
            yb, NTOT, 1, (long)CI_ * NTOT,
            out, (long)CC * NTOT,
            CC, NTOT, CI_,
            bw, 0.f, gamma, beta, rmean, rvar, x, (long)CC * NTOT);
    }
}

// round 9
// speedup vs baseline: 8.7347x; 1.2020x over previous
#include <cuda_runtime.h>
#include <cuda_bf16.h>
#include <math.h>
#include <stdint.h>

// Problem constants
#define BB   8
#define CC   1024
#define CI_  512
#define DD   256
#define TT   8
#define HH   28
#define WW   28
#define NTOT 6272
#define NP   1568
#define BH   16

// Scratch (device globals: allocation-free), all GEMM operands in bf16
__device__ __nv_bfloat16 b_x [(long)BB * CC * NTOT];
__device__ __nv_bfloat16 b_xp[(long)BB * CC * NP];
__device__ __nv_bfloat16 b_w [(long)4 * CI_ * CC];     // Wg|Wth|Wph|Ww
__device__ __nv_bfloat16 b_g [(long)BB * CI_ * NP];
__device__ __nv_bfloat16 b_ph[(long)BB * CI_ * NP];
__device__ __nv_bfloat16 b_th[(long)BB * CI_ * NTOT];
__device__ __nv_bfloat16 b_y [(long)BB * CI_ * NTOT];
__device__ __nv_bfloat16 b_f [(long)BH * NTOT * NP];

__device__ __forceinline__ uint32_t smem_u32(const void* p) {
    uint32_t a;
    asm("{ .reg .u64 t; cvta.to.shared.u64 t, %1; cvt.u32.u64 %0, t; }"
        : "=r"(a) : "l"(p));
    return a;
}
__device__ __forceinline__ void cp16(uint32_t dst, const void* src, bool p) {
    int sz = p ? 16 : 0;
    asm volatile("cp.async.cg.shared.global [%0], [%1], 16, %2;"
                 :: "r"(dst), "l"(src), "r"(sz) : "memory");
}
#define CP_COMMIT() asm volatile("cp.async.commit_group;" ::: "memory")
#define CP_WAIT1()  asm volatile("cp.async.wait_group 1;" ::: "memory")

__device__ __forceinline__ void ldsm_x4(uint32_t addr, uint32_t* r) {
    asm volatile("ldmatrix.sync.aligned.m8n8.x4.shared.b16 {%0,%1,%2,%3}, [%4];"
                 : "=r"(r[0]), "=r"(r[1]), "=r"(r[2]), "=r"(r[3]) : "r"(addr));
}
__device__ __forceinline__ void ldsm_x4_t(uint32_t addr, uint32_t* r) {
    asm volatile("ldmatrix.sync.aligned.m8n8.x4.trans.shared.b16 {%0,%1,%2,%3}, [%4];"
                 : "=r"(r[0]), "=r"(r[1]), "=r"(r[2]), "=r"(r[3]) : "r"(addr));
}

__device__ __forceinline__ uint32_t bpack(float a, float b) {
    __nv_bfloat162 t = __floats2bfloat162_rn(a, b);
    return *(uint32_t*)&t;
}

__device__ __forceinline__ void mma_bf16(float* c, const uint32_t* a, const uint32_t* b) {
    asm volatile(
        "mma.sync.aligned.m16n8k16.row.col.f32.bf16.bf16.f32 "
        "{%0,%1,%2,%3}, {%4,%5,%6,%7}, {%8,%9}, {%0,%1,%2,%3};"
        : "+f"(c[0]), "+f"(c[1]), "+f"(c[2]), "+f"(c[3])
        : "r"(a[0]), "r"(a[1]), "r"(a[2]), "r"(a[3]), "r"(b[0]), "r"(b[1]));
}

// ---------------------------------------------------------------------------
// fp32 -> bf16 convert (n4 float4 elements)
// ---------------------------------------------------------------------------
__global__ void cvtb_kernel(const float4* __restrict__ in,
                            __nv_bfloat162* __restrict__ out, long n4) {
    long i = (long)blockIdx.x * blockDim.x + threadIdx.x;
    if (i >= n4) return;
    float4 v = in[i];
    out[2 * i]     = __floats2bfloat162_rn(v.x, v.y);
    out[2 * i + 1] = __floats2bfloat162_rn(v.z, v.w);
}

// ---------------------------------------------------------------------------
// MaxPool3d(1,2,2) -> bf16
// ---------------------------------------------------------------------------
__global__ void maxpool_kernel(const float* __restrict__ x) {
    long idx = (long)blockIdx.x * blockDim.x + threadIdx.x;
    const long total = (long)BB * CC * TT * 14 * 14;
    if (idx >= total) return;
    int ow = idx % 14;
    int oh = (idx / 14) % 14;
    long rest = idx / 196;
    long base = rest * (HH * WW) + (long)(oh * 2) * WW + ow * 2;
    float m0 = fmaxf(x[base], x[base + 1]);
    float m1 = fmaxf(x[base + WW], x[base + WW + 1]);
    b_xp[idx] = __float2bfloat16_rn(fmaxf(m0, m1));
}

// ---------------------------------------------------------------------------
// cp.async 3-stage bf16 mma.sync GEMM (m16n8k16) with ldmatrix fragments.
// C[m,n] = sum_k A'[m*am+k*ak] * B'[k*bk+n*bn]; BM=128, BN=128, BK=32; 8 warps
// (warp grid 4m x 2n, warp tile 32x64).
// AKI: k contig in A -> smem [m][k] rows 80B; else [k][m] rows 272B (trans LDSM).
// BKI: k contig in B -> smem [n][k] rows 80B; else [k][n] rows 272B (trans LDSM).
// EPI: 0=+bias->bf16; 1=*scale->bf16; 2=plain->bf16; 3=BN+residual->fp32.
// Requires M%128==0, K%32==0, N%8==0 (N tail bounds-checked).
// ---------------------------------------------------------------------------
#define SM_BYTES 61440

template<int EPI, bool AKI, bool BKI>
__global__ void __launch_bounds__(256, 2)
tgemm_kernel(const __nv_bfloat16* __restrict__ A, long am, long ak, long ab,
             const __nv_bfloat16* __restrict__ Bp, long bk, long bn, long bb,
             void* __restrict__ Cp, long cb,
             int M, int N, int K,
             const float* __restrict__ bias, float scale,
             const float* __restrict__ gamma, const float* __restrict__ beta,
             const float* __restrict__ rmean, const float* __restrict__ rvar,
             const float* __restrict__ xres, long xb)
{
    extern __shared__ char smc[];
    constexpr int A_BYTES = AKI ? 128 * 80 : 32 * 272;
    constexpr int B_BYTES = BKI ? 128 * 80 : 32 * 272;
    constexpr int STG_BYTES = A_BYTES + B_BYTES;

    const int tid  = threadIdx.x;
    const int wid  = tid >> 5;
    const int lane = tid & 31;
    const int gq   = lane >> 2;
    const int qq   = lane & 3;
    const int warp_m = (wid & 3) * 32;
    const int warp_n = (wid >> 2) * 64;

    const int bz = blockIdx.z;
    const __nv_bfloat16* Ab = A  + ab * bz;
    const __nv_bfloat16* Bb = Bp + bb * bz;
    const int m0 = blockIdx.y * 128;
    const int n0 = blockIdx.x * 128;

    const uint32_t smb = smem_u32(smc);

    // ldmatrix per-lane tile addressing: t = tile index (0..3), rr = row in tile
    const int t  = lane >> 3;
    const int rr = lane & 7;
    uint32_t a_off[2], b_off;
#pragma unroll
    for (int mf = 0; mf < 2; mf++) {
        if (AKI)
            a_off[mf] = (uint32_t)((warp_m + mf * 16 + (t & 1) * 8 + rr) * 80 + (t >> 1) * 16);
        else
            a_off[mf] = (uint32_t)(((t >> 1) * 8 + rr) * 272 + (warp_m + mf * 16 + (t & 1) * 8) * 2);
    }
    if (BKI)
        b_off = (uint32_t)((warp_n + (t >> 1) * 8 + rr) * 80 + (t & 1) * 16);
    else
        b_off = (uint32_t)(((t & 1) * 8 + rr) * 272 + (warp_n + (t >> 1) * 8) * 2);

    float acc[2][8][4];
#pragma unroll
    for (int i = 0; i < 2; i++)
#pragma unroll
        for (int j = 0; j < 8; j++)
#pragma unroll
            for (int r = 0; r < 4; r++) acc[i][j][r] = 0.f;

    const int KT = K >> 5;

    auto issue = [&](int kt, int s) {
        const int k0 = kt << 5;
        uint32_t sa = smb + (uint32_t)s * STG_BYTES;
        uint32_t sb = sa + A_BYTES;
#pragma unroll
        for (int j = 0; j < 2; j++) {
            int e = tid + j * 256;
            if (AKI) {
                int m = e >> 2, ch = e & 3;
                cp16(sa + m * 80 + ch * 16,
                     Ab + (long)(m0 + m) * am + (k0 + ch * 8), true);
            } else {
                int kk = e >> 4, ch = e & 15;
                cp16(sa + kk * 272 + ch * 16,
                     Ab + (long)(k0 + kk) * ak + (m0 + ch * 8), true);
            }
        }
#pragma unroll
        for (int j = 0; j < 2; j++) {
            int e = tid + j * 256;
            if (BKI) {
                int n = e >> 2, ch = e & 3;
                bool p = (n0 + n) < N;
                int nc = p ? (n0 + n) : (N - 1);
                cp16(sb + n * 80 + ch * 16,
                     Bb + (long)nc * bn + (k0 + ch * 8), p);
            } else {
                int kk = e >> 4, ch = e & 15;
                bool p = (n0 + ch * 8) < N;
                int nc = p ? (n0 + ch * 8) : (N - 8);
                cp16(sb + kk * 272 + ch * 16,
                     Bb + (long)(k0 + kk) * bk + nc, p);
            }
        }
    };

    auto compute = [&](int s) {
        const uint32_t sa = smb + (uint32_t)s * STG_BYTES;
        const uint32_t sb = sa + A_BYTES;
#pragma unroll
        for (int ks = 0; ks < 2; ks++) {
            uint32_t afr[2][4];
#pragma unroll
            for (int mf = 0; mf < 2; mf++) {
                if (AKI) ldsm_x4  (sa + a_off[mf] + ks * 32,   afr[mf]);
                else     ldsm_x4_t(sa + a_off[mf] + ks * 4352, afr[mf]);
            }
#pragma unroll
            for (int nf2 = 0; nf2 < 4; nf2++) {
                uint32_t bfr[4];
                if (BKI) ldsm_x4  (sb + b_off + nf2 * 1280 + ks * 32,   bfr);
                else     ldsm_x4_t(sb + b_off + nf2 * 32   + ks * 4352, bfr);
                mma_bf16(acc[0][2 * nf2],     afr[0], bfr);
                mma_bf16(acc[1][2 * nf2],     afr[1], bfr);
                mma_bf16(acc[0][2 * nf2 + 1], afr[0], bfr + 2);
                mma_bf16(acc[1][2 * nf2 + 1], afr[1], bfr + 2);
            }
        }
    };

    // prologue
    issue(0, 0);
    CP_COMMIT();
    if (KT > 1) issue(1, 1);
    CP_COMMIT();

    for (int kt = 0; kt < KT; kt++) {
        CP_WAIT1();
        __syncthreads();
        if (kt + 2 < KT) issue(kt + 2, (kt + 2) % 3);
        CP_COMMIT();
        compute(kt % 3);
    }

    // epilogue
    if (EPI == 3) {
        float* Cb = (float*)Cp + cb * bz;
#pragma unroll
        for (int mf = 0; mf < 2; mf++) {
            int r1 = m0 + warp_m + mf * 16 + gq;
            int r2 = r1 + 8;
            float b1 = bias[r1], b2 = bias[r2];
            float i1 = gamma[r1] * rsqrtf(rvar[r1] + 1e-5f);
            float i2 = gamma[r2] * rsqrtf(rvar[r2] + 1e-5f);
            float s1 = beta[r1] - rmean[r1] * i1;
            float s2 = beta[r2] - rmean[r2] * i2;
#pragma unroll
            for (int nf = 0; nf < 8; nf++) {
                int col = n0 + warp_n + nf * 8 + 2 * qq;
                if (col >= N) continue;
                const float* xr = xres + xb * bz;
                float2 x1 = *(const float2*)(xr + (long)r1 * N + col);
                float2 x2 = *(const float2*)(xr + (long)r2 * N + col);
                float v0 = (acc[mf][nf][0] + b1) * i1 + s1 + x1.x;
                float v1 = (acc[mf][nf][1] + b1) * i1 + s1 + x1.y;
                float v2 = (acc[mf][nf][2] + b2) * i2 + s2 + x2.x;
                float v3 = (acc[mf][nf][3] + b2) * i2 + s2 + x2.y;
                *(float2*)(Cb + (long)r1 * N + col) = make_float2(v0, v1);
                *(float2*)(Cb + (long)r2 * N + col) = make_float2(v2, v3);
            }
        }
    } else {
        __nv_bfloat16* Cb = (__nv_bfloat16*)Cp + cb * bz;
#pragma unroll
        for (int mf = 0; mf < 2; mf++) {
            int r1 = m0 + warp_m + mf * 16 + gq;
            int r2 = r1 + 8;
            float b1 = 0.f, b2 = 0.f;
            if (EPI == 0) { b1 = bias[r1]; b2 = bias[r2]; }
#pragma unroll
            for (int nf = 0; nf < 8; nf++) {
                int col = n0 + warp_n + nf * 8 + 2 * qq;
                if (col >= N) continue;
                float v0 = acc[mf][nf][0], v1 = acc[mf][nf][1];
                float v2 = acc[mf][nf][2], v3 = acc[mf][nf][3];
                if (EPI == 0) { v0 += b1; v1 += b1; v2 += b2; v3 += b2; }
                if (EPI == 1) { v0 *= scale; v1 *= scale; v2 *= scale; v3 *= scale; }
                *(uint32_t*)(Cb + (long)r1 * N + col) = bpack(v0, v1);
                *(uint32_t*)(Cb + (long)r2 * N + col) = bpack(v2, v3);
            }
        }
    }
}

// ---------------------------------------------------------------------------
// Single-pass row softmax on bf16 rows of width NP. One read + one write.
// ---------------------------------------------------------------------------
__global__ void softmax_kernel(__nv_bfloat162* __restrict__ f) {
    __nv_bfloat162* p = f + (long)blockIdx.x * (NP / 2);
    const int tid = threadIdx.x;          // 128 threads
    __shared__ float red[128];

    // NP/2 = 784 = 6*128 + 16
    uint32_t v[7];
    const bool has7 = (tid < 16);

#pragma unroll
    for (int j = 0; j < 7; j++) {
        int i = tid + j * 128;
        if (j < 6 || has7) v[j] = *(uint32_t*)&p[i];
    }

    float mx = -INFINITY;
#pragma unroll
    for (int j = 0; j < 7; j++) {
        if (j < 6 || has7) {
            float2 t = __bfloat1622float2(*(__nv_bfloat162*)&v[j]);
            mx = fmaxf(mx, fmaxf(t.x, t.y));
        }
    }
    red[tid] = mx; __syncthreads();
    for (int s = 64; s > 0; s >>= 1) {
        if (tid < s) red[tid] = fmaxf(red[tid], red[tid + s]);
        __syncthreads();
    }
    mx = red[0]; __syncthreads();

    float sum = 0.f;
#pragma unroll
    for (int j = 0; j < 7; j++) {
        if (j < 6 || has7) {
            float2 t = __bfloat1622float2(*(__nv_bfloat162*)&v[j]);
            float e0 = __expf(t.x - mx);
            float e1 = __expf(t.y - mx);
            sum += e0 + e1;
            v[j] = bpack(e0, e1);
        }
    }
    red[tid] = sum; __syncthreads();
    for (int s = 64; s > 0; s >>= 1) {
        if (tid < s) red[tid] += red[tid + s];
        __syncthreads();
    }
    float inv = 1.f / red[0];

#pragma unroll
    for (int j = 0; j < 7; j++) {
        int i = tid + j * 128;
        if (j < 6 || has7) {
            float2 t = __bfloat1622float2(*(__nv_bfloat162*)&v[j]);
            uint32_t o = bpack(t.x * inv, t.y * inv);
            *(uint32_t*)&p[i] = o;
        }
    }
}

// ---------------------------------------------------------------------------
extern "C" void kernel_launch(void* const* d_in, const int* in_sizes, int n_in,
                              void* d_out, int out_size)
{
    const float* x     = (const float*)d_in[0];
    const float* Wg    = (const float*)d_in[1];
    const float* bg    = (const float*)d_in[2];
    const float* Wth   = (const float*)d_in[3];
    const float* bth   = (const float*)d_in[4];
    const float* Wph   = (const float*)d_in[5];
    const float* bph   = (const float*)d_in[6];
    const float* Ww    = (const float*)d_in[7];
    const float* bw    = (const float*)d_in[8];
    const float* gamma = (const float*)d_in[9];
    const float* beta  = (const float*)d_in[10];
    const float* rmean = (const float*)d_in[11];
    const float* rvar  = (const float*)d_in[12];
    float* out = (float*)d_out;

    __nv_bfloat16 *xb, *xpb, *wb, *gb, *phb, *thb, *yb, *fb;
    cudaGetSymbolAddress((void**)&xb,  b_x);
    cudaGetSymbolAddress((void**)&xpb, b_xp);
    cudaGetSymbolAddress((void**)&wb,  b_w);
    cudaGetSymbolAddress((void**)&gb,  b_g);
    cudaGetSymbolAddress((void**)&phb, b_ph);
    cudaGetSymbolAddress((void**)&thb, b_th);
    cudaGetSymbolAddress((void**)&yb,  b_y);
    cudaGetSymbolAddress((void**)&fb,  b_f);

    cudaFuncSetAttribute(tgemm_kernel<0, true,  false>, cudaFuncAttributeMaxDynamicSharedMemorySize, SM_BYTES);
    cudaFuncSetAttribute(tgemm_kernel<1, false, false>, cudaFuncAttributeMaxDynamicSharedMemorySize, SM_BYTES);
    cudaFuncSetAttribute(tgemm_kernel<2, true,  true >, cudaFuncAttributeMaxDynamicSharedMemorySize, SM_BYTES);
    cudaFuncSetAttribute(tgemm_kernel<3, true,  false>, cudaFuncAttributeMaxDynamicSharedMemorySize, SM_BYTES);

    const long WSZ = (long)CI_ * CC;   // 524288

    // 0) bf16 operand conversion
    {
        long n4 = (long)BB * CC * NTOT / 4;
        cvtb_kernel<<<(unsigned)((n4 + 255) / 256), 256>>>(
            (const float4*)x, (__nv_bfloat162*)xb, n4);
        long w4 = WSZ / 4;
        cvtb_kernel<<<(unsigned)((w4 + 255) / 256), 256>>>((const float4*)Wg,  (__nv_bfloat162*)(wb),           w4);
        cvtb_kernel<<<(unsigned)((w4 + 255) / 256), 256>>>((const float4*)Wth, (__nv_bfloat162*)(wb + WSZ),     w4);
        cvtb_kernel<<<(unsigned)((w4 + 255) / 256), 256>>>((const float4*)Wph, (__nv_bfloat162*)(wb + 2 * WSZ), w4);
        cvtb_kernel<<<(unsigned)((w4 + 255) / 256), 256>>>((const float4*)Ww,  (__nv_bfloat162*)(wb + 3 * WSZ), w4);
    }

    // 1) maxpool -> bf16
    {
        long total = (long)BB * CC * NP;
        maxpool_kernel<<<(unsigned)((total + 255) / 256), 256>>>(x);
    }

    // 2) g = Wg @ xp + bg     (M=512, N=1568, K=1024, batch 8)
    {
        dim3 grid((NP + 127) / 128, CI_ / 128, BB);
        tgemm_kernel<0, true, false><<<grid, 256, SM_BYTES>>>(
            wb, CC, 1, 0,
            xpb, NP, 1, (long)CC * NP,
            gb, (long)CI_ * NP,
            CI_, NP, CC,
            bg, 0.f, nullptr, nullptr, nullptr, nullptr, nullptr, 0);
    }
    // 3) ph = Wph @ xp + bph
    {
        dim3 grid((NP + 127) / 128, CI_ / 128, BB);
        tgemm_kernel<0, true, false><<<grid, 256, SM_BYTES>>>(
            wb + 2 * WSZ, CC, 1, 0,
            xpb, NP, 1, (long)CC * NP,
            phb, (long)CI_ * NP,
            CI_, NP, CC,
            bph, 0.f, nullptr, nullptr, nullptr, nullptr, nullptr, 0);
    }
    // 4) th = Wth @ x + bth   (M=512, N=6272, K=1024, batch 8)
    {
        dim3 grid(NTOT / 128, CI_ / 128, BB);
        tgemm_kernel<0, true, false><<<grid, 256, SM_BYTES>>>(
            wb + WSZ, CC, 1, 0,
            xb, NTOT, 1, (long)CC * NTOT,
            thb, (long)CI_ * NTOT,
            CI_, NTOT, CC,
            bth, 0.f, nullptr, nullptr, nullptr, nullptr, nullptr, 0);
    }
    // 5) f = th^T @ ph * d^-0.5  (M=6272, N=1568, K=256, batch 16)
    {
        dim3 grid((NP + 127) / 128, NTOT / 128, BH);
        tgemm_kernel<1, false, false><<<grid, 256, SM_BYTES>>>(
            thb, 1, NTOT, (long)DD * NTOT,
            phb, NP, 1, (long)DD * NP,
            fb, (long)NTOT * NP,
            NTOT, NP, DD,
            nullptr, 0.0625f, nullptr, nullptr, nullptr, nullptr, nullptr, 0);
    }
    // 6) softmax (single-pass)
    softmax_kernel<<<BH * NTOT, 128>>>((__nv_bfloat162*)fb);

    // 7) y = g @ a^T          (M=256, N=6272, K=1568, batch 16)
    {
        dim3 grid(NTOT / 128, DD / 128, BH);
        tgemm_kernel<2, true, true><<<grid, 256, SM_BYTES>>>(
            gb, NP, 1, (long)DD * NP,
            fb, 1, NP, (long)NTOT * NP,
            yb, (long)DD * NTOT,
            DD, NTOT, NP,
            nullptr, 0.f, nullptr, nullptr, nullptr, nullptr, nullptr, 0);
    }
    // 8) out = BN(Ww @ y + bw) + x   (M=1024, N=6272, K=512, batch 8)
    {
        dim3 grid(NTOT / 128, CC / 128, BB);
        tgemm_kernel<3, true, false><<<grid, 256, SM_BYTES>>>(
            wb + 3 * WSZ, CI_, 1, 0,
            yb, NTOT, 1, (long)CI_ * NTOT,
            out, (long)CC * NTOT,
            CC, NTOT, CI_,
            bw, 0.f, gamma, beta, rmean, rvar, x, (long)CC * NTOT);
    }
}